// round 12
// baseline (speedup 1.0000x reference)
#include <cuda_runtime.h>
#include <cuda_bf16.h>
#include <cstdint>
#include <math.h>
#include <math_constants.h>

typedef unsigned int       u32;
typedef unsigned long long u64;

// ---------------- problem constants ----------------
#define QLEN   2500
#define NKLEN  6336
#define DMODEL 128
#define NHEADS 4
#define DHEAD  32
#define SPLITS 11
#define TPS    18           // 198 = 11 * 18 key tiles, exact
#define NKT    198
#define ATTN_SCALE 0.17677669529663688f
#define NEG_BIG (-3.402823466e38f)   // float32 finfo.min (reference semantics)

// attention pipeline smem layout (per stage)
#define KS_OFF   0
#define VS_OFF   10240
#define WS_OFF   20480
#define BV_OFF   25088
#define STAGEB   29696
#define NSTAGE   3

// ---------------- scratch ----------------
__device__ __nv_bfloat16 g_qbf[NHEADS * QLEN * DHEAD];
__device__ __nv_bfloat16 g_kbf[NHEADS * NKLEN * DHEAD];
__device__ __nv_bfloat16 g_vbf[NHEADS * NKLEN * DHEAD];
__device__ float g_pm[SPLITS * NHEADS * QLEN];
__device__ float g_ps[SPLITS * NHEADS * QLEN];
__device__ float g_pacc[SPLITS * NHEADS * QLEN * DHEAD];
// transposed weights: wT[d][col]
__device__ float g_wqT[128 * 128];
__device__ float g_wkT[128 * 128];
__device__ float g_wvT[128 * 128];
__device__ float g_wpT[128 * 128];
__device__ float g_w1T[128 * 256];
__device__ float g_w2T[256 * 128];

// ---------------- helpers ----------------
__device__ __forceinline__ u32 packbf(float lo, float hi) {
    u32 r;
    asm("cvt.rn.bf16x2.f32 %0, %1, %2;" : "=r"(r) : "f"(hi), "f"(lo));
    return r;
}

// Fast exp for x <= 0 (softmax path): FMA-pipe only, no MUFU/CVT.
// exp(x) = 2^y, y = x*log2e clamped at -120; n = round(y) via magic constant,
// f = y-n in [-0.5,0.5]; 2^f by degree-5 Taylor (rel err ~2.4e-6);
// exponent spliced with integer add.
__device__ __forceinline__ float expf_fast(float x) {
    float y = fmaxf(x * 1.4426950408889634f, -120.f);
    float z = __fadd_rn(y, 12582912.f);              // 2^23 + 2^22 magic
    int   n = __float_as_int(z) - 0x4B400000;
    float nf = __fadd_rn(z, -12582912.f);
    float f = __fadd_rn(y, -nf);
    float p = 1.3333558146e-3f;
    p = __fmaf_rn(p, f, 9.6181291076e-3f);
    p = __fmaf_rn(p, f, 5.5504108664e-2f);
    p = __fmaf_rn(p, f, 2.4022650696e-1f);
    p = __fmaf_rn(p, f, 6.9314718056e-1f);
    p = __fmaf_rn(p, f, 1.0f);
    return __int_as_float(__float_as_int(p) + (n << 23));
}

__device__ __forceinline__ void mma16816(float (&c)[4],
                                         u32 a0, u32 a1, u32 a2, u32 a3,
                                         u32 b0, u32 b1) {
    asm volatile(
        "mma.sync.aligned.m16n8k16.row.col.f32.bf16.bf16.f32 "
        "{%0,%1,%2,%3}, {%4,%5,%6,%7}, {%8,%9}, {%0,%1,%2,%3};"
        : "+f"(c[0]), "+f"(c[1]), "+f"(c[2]), "+f"(c[3])
        : "r"(a0), "r"(a1), "r"(a2), "r"(a3), "r"(b0), "r"(b1));
}

__device__ __forceinline__ void cpa16(void* dst, const void* src) {
    u32 d = (u32)__cvta_generic_to_shared(dst);
    asm volatile("cp.async.cg.shared.global [%0], [%1], 16;" :: "r"(d), "l"(src));
}
__device__ __forceinline__ void cp_commit() { asm volatile("cp.async.commit_group;"); }
__device__ __forceinline__ void cp_wait1()  { asm volatile("cp.async.wait_group 1;"); }

// ============================================================================
// Kernel 0: transpose weights into [d][col] layout (coalesced GEMM reads)
// ============================================================================
__global__ void __launch_bounds__(256)
prep_weights(const float* __restrict__ wq, const float* __restrict__ wk,
             const float* __restrict__ wv, const float* __restrict__ wp,
             const float* __restrict__ w1, const float* __restrict__ w2)
{
    int idx = blockIdx.x * 256 + threadIdx.x;    // 0..32767
    if (idx < 16384) {
        int r = idx >> 7, c = idx & 127;         // source [r][c] -> dst [c][r]
        g_wqT[c * 128 + r] = wq[idx];
        g_wkT[c * 128 + r] = wk[idx];
        g_wvT[c * 128 + r] = wv[idx];
        g_wpT[c * 128 + r] = wp[idx];
    }
    {   // w1: [256][128] -> [128][256]
        int r = idx >> 7, c = idx & 127;
        g_w1T[c * 256 + r] = w1[idx];
    }
    {   // w2: [128][256] -> [256][128]
        int r = idx >> 8, c = idx & 255;
        g_w2T[c * 128 + r] = w2[idx];
    }
}

// ============================================================================
// LN + 128x128 GEMM body (transposed weights) -> bf16 planar [h][pos][32]
// ============================================================================
__device__ __forceinline__ void ln_gemm_body(
    const float* __restrict__ x, int npos, int inner_pos,
    const float* __restrict__ gam, const float* __restrict__ bet,
    const float* __restrict__ wT, const float* __restrict__ bw,
    __nv_bfloat16* __restrict__ outb, int pos0,
    float (*xs)[132], float* mu, float* rs)
{
    const int tid = threadIdx.x;

    #pragma unroll
    for (int it = 0; it < 16; it++) {
        int idx = tid + it * 256;
        int d = idx >> 5, j = idx & 31;
        int pos = pos0 + j;
        float v = 0.f;
        if (pos < npos) {
            int n = pos / inner_pos;
            int p = pos - n * inner_pos;
            v = x[((size_t)n * DMODEL + d) * (size_t)inner_pos + p];
        }
        xs[j][d] = v;
    }
    __syncthreads();

    {
        const int j = tid >> 3, ls = tid & 7;
        float mm = 0.f;
        #pragma unroll
        for (int d = ls; d < 128; d += 8) mm += xs[j][d];
        mm += __shfl_xor_sync(0xffffffffu, mm, 1);
        mm += __shfl_xor_sync(0xffffffffu, mm, 2);
        mm += __shfl_xor_sync(0xffffffffu, mm, 4);
        mm *= (1.f / 128.f);
        float vv = 0.f;
        #pragma unroll
        for (int d = ls; d < 128; d += 8) { float t = xs[j][d] - mm; vv += t * t; }
        vv += __shfl_xor_sync(0xffffffffu, vv, 1);
        vv += __shfl_xor_sync(0xffffffffu, vv, 2);
        vv += __shfl_xor_sync(0xffffffffu, vv, 4);
        vv *= (1.f / 128.f);
        if (ls == 0) { mu[j] = mm; rs[j] = rsqrtf(vv + 1e-5f); }
    }
    __syncthreads();

    #pragma unroll
    for (int it = 0; it < 16; it++) {
        int idx = tid + it * 256;
        int j = idx >> 7, d = idx & 127;
        xs[j][d] = (xs[j][d] - mu[j]) * rs[j] * gam[d] + bet[d];
    }
    __syncthreads();

    float acc[4][4];
    #pragma unroll
    for (int r = 0; r < 4; r++)
        #pragma unroll
        for (int c = 0; c < 4; c++) acc[r][c] = 0.f;

    const int j0 = (tid >> 5) * 4;
    const int i0 = (tid & 31) * 4;
    for (int d0 = 0; d0 < 128; d0 += 4) {
        float4 xv[4];
        #pragma unroll
        for (int r = 0; r < 4; r++) xv[r] = *(const float4*)&xs[j0 + r][d0];
        #pragma unroll
        for (int dd = 0; dd < 4; dd++) {
            float4 wv = __ldg((const float4*)&wT[(d0 + dd) * 128 + i0]);
            #pragma unroll
            for (int r = 0; r < 4; r++) {
                float xr = (dd == 0) ? xv[r].x : (dd == 1) ? xv[r].y : (dd == 2) ? xv[r].z : xv[r].w;
                acc[r][0] += xr * wv.x;
                acc[r][1] += xr * wv.y;
                acc[r][2] += xr * wv.z;
                acc[r][3] += xr * wv.w;
            }
        }
    }
    const int h = i0 >> 5;
    const int dbase = i0 & 31;
    #pragma unroll
    for (int r = 0; r < 4; r++) {
        int pos = pos0 + j0 + r;
        if (pos < npos) {
            uint2 u;
            u.x = packbf(acc[r][0] + bw[i0 + 0], acc[r][1] + bw[i0 + 1]);
            u.y = packbf(acc[r][2] + bw[i0 + 2], acc[r][3] + bw[i0 + 3]);
            *(uint2*)&outb[((size_t)h * npos + pos) * DHEAD + dbase] = u;
        }
    }
}

// ============================================================================
// Kernel 1: fused QKV projections — one launch, 475 blocks
// ============================================================================
__global__ void __launch_bounds__(256)
qkv_fused(const float* __restrict__ q, const float* __restrict__ k, const float* __restrict__ v,
          const float* __restrict__ qn_g, const float* __restrict__ qn_b,
          const float* __restrict__ kn_g, const float* __restrict__ kn_b,
          const float* __restrict__ vn_g, const float* __restrict__ vn_b,
          const float* __restrict__ bq, const float* __restrict__ bk,
          const float* __restrict__ bv)
{
    __shared__ float xs[32][132];
    __shared__ float mu[32], rs[32];
    int b = blockIdx.x;
    if (b < 79) {
        ln_gemm_body(q, QLEN, QLEN, qn_g, qn_b, g_wqT, bq, g_qbf, b * 32, xs, mu, rs);
    } else if (b < 277) {
        ln_gemm_body(k, NKLEN, 1056, kn_g, kn_b, g_wkT, bk, g_kbf, (b - 79) * 32, xs, mu, rs);
    } else {
        ln_gemm_body(v, NKLEN, 1056, vn_g, vn_b, g_wvT, bv, g_vbf, (b - 277) * 32, xs, mu, rs);
    }
}

// ============================================================================
// Kernel 2: HMMA bf16 flash attention, split-K, 3-stage cp.async pipeline.
// K fed via ldmatrix.x2; softmax exp on FMA pipe (expf_fast).
// ============================================================================
__device__ __forceinline__ void attn_issue_tile(char* stg, int qt, int k0,
                                                const float* __restrict__ Wl,
                                                const int* __restrict__ vis, int tid)
{
    #pragma unroll
    for (int c = tid; c < 512; c += 256) {
        int hh = c >> 7, key = (c >> 2) & 31, part = c & 3;
        size_t srcoff = ((size_t)(hh * NKLEN + k0 + key)) * DHEAD + part * 8;
        int doff = hh * 2560 + key * 80 + part * 16;
        cpa16(stg + KS_OFF + doff, g_kbf + srcoff);
        cpa16(stg + VS_OFF + doff, g_vbf + srcoff);
    }
    {
        int row = tid >> 3, part = tid & 7;
        int qq = qt * 32 + row; if (qq >= QLEN) qq = QLEN - 1;
        cpa16(stg + WS_OFF + row * 144 + part * 16, Wl  + (size_t)qq * NKLEN + k0 + part * 4);
        cpa16(stg + BV_OFF + row * 144 + part * 16, vis + (size_t)qq * NKLEN + k0 + part * 4);
    }
}

__global__ void __launch_bounds__(256, 2)
attn_kernel(const float* __restrict__ Wl, const int* __restrict__ vis)
{
    extern __shared__ char dsm[];

    const int tid = threadIdx.x;
    const int lane = tid & 31;
    const int wid = tid >> 5;
    const int h = wid & 3;
    const int rg = wid >> 2;
    const int g = lane >> 2;
    const int tx = lane & 3;
    const int qt = blockIdx.x;
    const int split = blockIdx.y;

    const int q0 = qt * 32 + rg * 16;
    const int r_lo = q0 + g;
    const int r_hi = q0 + g + 8;

    u32 aQ[2][4];
    #pragma unroll
    for (int kc = 0; kc < 2; kc++) {
        int c0 = kc * 16 + 2 * tx;
        aQ[kc][0] = (r_lo < QLEN) ? *(const u32*)&g_qbf[((size_t)h * QLEN + r_lo) * DHEAD + c0]     : 0u;
        aQ[kc][1] = (r_hi < QLEN) ? *(const u32*)&g_qbf[((size_t)h * QLEN + r_hi) * DHEAD + c0]     : 0u;
        aQ[kc][2] = (r_lo < QLEN) ? *(const u32*)&g_qbf[((size_t)h * QLEN + r_lo) * DHEAD + c0 + 8] : 0u;
        aQ[kc][3] = (r_hi < QLEN) ? *(const u32*)&g_qbf[((size_t)h * QLEN + r_hi) * DHEAD + c0 + 8] : 0u;
    }

    float acc[4][4];
    #pragma unroll
    for (int nc = 0; nc < 4; nc++)
        #pragma unroll
        for (int i = 0; i < 4; i++) acc[nc][i] = 0.f;
    float m0 = -CUDART_INF_F, m1 = -CUDART_INF_F, s0 = 0.f, s1 = 0.f;

    const int t0 = split * TPS;

    attn_issue_tile(dsm + 0 * STAGEB, qt, (t0 + 0) * 32, Wl, vis, tid);
    cp_commit();
    attn_issue_tile(dsm + 1 * STAGEB, qt, (t0 + 1) * 32, Wl, vis, tid);
    cp_commit();

    // ldmatrix row selector for K: lanes 0-7 -> matrix0 rows, 8-15 -> matrix1
    const int lm = lane & 15;
    const int lmrow = lm & 7;
    const int lmhalf = (lm >> 3) * 16;   // byte offset of second 8-col block

    for (int i = 0; i < TPS; i++) {
        cp_wait1();
        __syncthreads();
        char* stg = dsm + (i % NSTAGE) * STAGEB;

        float S[4][4];
        #pragma unroll
        for (int nc = 0; nc < 4; nc++) {
            S[nc][0] = 0.f; S[nc][1] = 0.f; S[nc][2] = 0.f; S[nc][3] = 0.f;
            #pragma unroll
            for (int kc = 0; kc < 2; kc++) {
                u32 kaddr = (u32)__cvta_generic_to_shared(
                    stg + KS_OFF + h * 2560 + (nc * 8 + lmrow) * 80 + kc * 32 + lmhalf);
                u32 b0, b1;
                asm volatile("ldmatrix.sync.aligned.m8n8.x2.shared.b16 {%0,%1}, [%2];"
                             : "=r"(b0), "=r"(b1) : "r"(kaddr));
                mma16816(S[nc], aQ[kc][0], aQ[kc][1], aQ[kc][2], aQ[kc][3], b0, b1);
            }
        }

        float l[4][4];
        const int wr_lo = rg * 16 + g;
        const int wr_hi = wr_lo + 8;
        #pragma unroll
        for (int nc = 0; nc < 4; nc++) {
            float2 wl = *(const float2*)(stg + WS_OFF + wr_lo * 144 + (nc * 8 + 2 * tx) * 4);
            float2 wh = *(const float2*)(stg + WS_OFF + wr_hi * 144 + (nc * 8 + 2 * tx) * 4);
            int2 bl = *(const int2*)(stg + BV_OFF + wr_lo * 144 + (nc * 8 + 2 * tx) * 4);
            int2 bh = *(const int2*)(stg + BV_OFF + wr_hi * 144 + (nc * 8 + 2 * tx) * 4);
            l[nc][0] = (bl.x == 0 ? NEG_BIG : S[nc][0] * ATTN_SCALE) * wl.x;
            l[nc][1] = (bl.y == 0 ? NEG_BIG : S[nc][1] * ATTN_SCALE) * wl.y;
            l[nc][2] = (bh.x == 0 ? NEG_BIG : S[nc][2] * ATTN_SCALE) * wh.x;
            l[nc][3] = (bh.y == 0 ? NEG_BIG : S[nc][3] * ATTN_SCALE) * wh.y;
        }

        float mx0 = fmaxf(fmaxf(l[0][0], l[0][1]), fmaxf(l[1][0], l[1][1]));
        mx0 = fmaxf(mx0, fmaxf(fmaxf(l[2][0], l[2][1]), fmaxf(l[3][0], l[3][1])));
        float mx1 = fmaxf(fmaxf(l[0][2], l[0][3]), fmaxf(l[1][2], l[1][3]));
        mx1 = fmaxf(mx1, fmaxf(fmaxf(l[2][2], l[2][3]), fmaxf(l[3][2], l[3][3])));
        mx0 = fmaxf(mx0, __shfl_xor_sync(0xffffffffu, mx0, 1));
        mx0 = fmaxf(mx0, __shfl_xor_sync(0xffffffffu, mx0, 2));
        mx1 = fmaxf(mx1, __shfl_xor_sync(0xffffffffu, mx1, 1));
        mx1 = fmaxf(mx1, __shfl_xor_sync(0xffffffffu, mx1, 2));
        float mn0 = fmaxf(m0, mx0);
        float mn1 = fmaxf(m1, mx1);
        float cr0 = expf_fast(m0 - mn0);
        float cr1 = expf_fast(m1 - mn1);
        m0 = mn0; m1 = mn1;
        s0 *= cr0; s1 *= cr1;
        #pragma unroll
        for (int nc = 0; nc < 4; nc++) {
            acc[nc][0] *= cr0; acc[nc][1] *= cr0;
            acc[nc][2] *= cr1; acc[nc][3] *= cr1;
        }
        float p[4][4];
        #pragma unroll
        for (int nc = 0; nc < 4; nc++) {
            p[nc][0] = expf_fast(l[nc][0] - m0);
            p[nc][1] = expf_fast(l[nc][1] - m0);
            p[nc][2] = expf_fast(l[nc][2] - m1);
            p[nc][3] = expf_fast(l[nc][3] - m1);
            s0 += p[nc][0] + p[nc][1];
            s1 += p[nc][2] + p[nc][3];
        }

        #pragma unroll
        for (int kc = 0; kc < 2; kc++) {
            u32 a0 = packbf(p[2 * kc][0],     p[2 * kc][1]);
            u32 a1 = packbf(p[2 * kc][2],     p[2 * kc][3]);
            u32 a2 = packbf(p[2 * kc + 1][0], p[2 * kc + 1][1]);
            u32 a3 = packbf(p[2 * kc + 1][2], p[2 * kc + 1][3]);
            int keyrow = kc * 16 + (lane & 15);
            #pragma unroll
            for (int nc = 0; nc < 4; nc++) {
                u32 addr = (u32)__cvta_generic_to_shared(
                    stg + VS_OFF + h * 2560 + keyrow * 80 + nc * 16);
                u32 b0, b1;
                asm volatile("ldmatrix.sync.aligned.m8n8.x2.trans.shared.b16 {%0,%1}, [%2];"
                             : "=r"(b0), "=r"(b1) : "r"(addr));
                mma16816(acc[nc], a0, a1, a2, a3, b0, b1);
            }
        }

        if (i + 2 < TPS)
            attn_issue_tile(dsm + ((i + 2) % NSTAGE) * STAGEB, qt, (t0 + i + 2) * 32, Wl, vis, tid);
        cp_commit();
    }

    s0 += __shfl_xor_sync(0xffffffffu, s0, 1);
    s0 += __shfl_xor_sync(0xffffffffu, s0, 2);
    s1 += __shfl_xor_sync(0xffffffffu, s1, 1);
    s1 += __shfl_xor_sync(0xffffffffu, s1, 2);

    const int base = (split * NHEADS + h) * QLEN;
    if (tx == 0) {
        if (r_lo < QLEN) { g_pm[base + r_lo] = m0; g_ps[base + r_lo] = s0; }
        if (r_hi < QLEN) { g_pm[base + r_hi] = m1; g_ps[base + r_hi] = s1; }
    }
    #pragma unroll
    for (int nc = 0; nc < 4; nc++) {
        if (r_lo < QLEN)
            *(float2*)&g_pacc[((size_t)(base + r_lo)) * DHEAD + nc * 8 + 2 * tx] =
                make_float2(acc[nc][0], acc[nc][1]);
        if (r_hi < QLEN)
            *(float2*)&g_pacc[((size_t)(base + r_hi)) * DHEAD + nc * 8 + 2 * tx] =
                make_float2(acc[nc][2], acc[nc][3]);
    }
}

// ============================================================================
// Kernel 3: fully fused tail — combine + proj + skip + pre-LN + fc1 + GELU
//           + fc2 + residual + post-LN + transposed store.
//           128 threads, 8 rows/block, 313 blocks.
// ============================================================================
#define TROWS 8
#define TTHREADS 128
__global__ void __launch_bounds__(TTHREADS)
tail_fused(const float* __restrict__ bproj, const float* __restrict__ skip,
           const float* __restrict__ pre_g, const float* __restrict__ pre_b,
           const float* __restrict__ b1, const float* __restrict__ b2,
           const float* __restrict__ post_g, const float* __restrict__ post_b,
           float* __restrict__ out)
{
    __shared__ float xs[TROWS][132];
    __shared__ float zs[TROWS][132];
    __shared__ float h1[TROWS][264];
    __shared__ float mu[TROWS], rs[TROWS];
    const int tid = threadIdx.x;
    const int pos0 = blockIdx.x * TROWS;

    // ---- combine split-K partials -> xs[row][h*32 + dh] (16 thr/row) ----
    {
        int row = tid >> 4;
        int h = (tid >> 2) & 3;
        int dh0 = (tid & 3) * 8;
        int qrow = pos0 + row;
        if (qrow < QLEN) {
            float M = -CUDART_INF_F;
            #pragma unroll
            for (int s = 0; s < SPLITS; s++)
                M = fmaxf(M, g_pm[(s * NHEADS + h) * QLEN + qrow]);
            float S = 0.f;
            float a[8];
            #pragma unroll
            for (int d = 0; d < 8; d++) a[d] = 0.f;
            #pragma unroll
            for (int s = 0; s < SPLITS; s++) {
                int p = (s * NHEADS + h) * QLEN + qrow;
                float e = expf_fast(g_pm[p] - M);
                S += g_ps[p] * e;
                const float* pa = &g_pacc[(size_t)p * DHEAD + dh0];
                #pragma unroll
                for (int d = 0; d < 8; d++) a[d] += pa[d] * e;
            }
            float inv = 1.f / S;
            #pragma unroll
            for (int d = 0; d < 8; d++) xs[row][h * 32 + dh0 + d] = a[d] * inv;
        } else {
            #pragma unroll
            for (int d = 0; d < 8; d++) xs[row][h * 32 + dh0 + d] = 0.f;
        }
    }
    __syncthreads();

    // ---- out-proj (128x128) + bias + skip -> zs; prefetch distance 8 ----
    {
        float acc[2][4];
        #pragma unroll
        for (int r = 0; r < 2; r++)
            #pragma unroll
            for (int c = 0; c < 4; c++) acc[r][c] = 0.f;

        const int j0 = (tid >> 5) * 2;
        const int i0 = (tid & 31) * 4;
        float4 wb[8];
        #pragma unroll
        for (int t = 0; t < 8; t++)
            wb[t] = __ldg((const float4*)&g_wpT[t * 128 + i0]);

        for (int d0 = 0; d0 < 128; d0 += 8) {
            float4 wc[8];
            #pragma unroll
            for (int t = 0; t < 8; t++) wc[t] = wb[t];
            if (d0 + 8 < 128) {
                #pragma unroll
                for (int t = 0; t < 8; t++)
                    wb[t] = __ldg((const float4*)&g_wpT[(d0 + 8 + t) * 128 + i0]);
            }
            #pragma unroll
            for (int t = 0; t < 8; t++) {
                float x0 = xs[j0][d0 + t];
                float x1 = xs[j0 + 1][d0 + t];
                acc[0][0] += x0 * wc[t].x; acc[0][1] += x0 * wc[t].y;
                acc[0][2] += x0 * wc[t].z; acc[0][3] += x0 * wc[t].w;
                acc[1][0] += x1 * wc[t].x; acc[1][1] += x1 * wc[t].y;
                acc[1][2] += x1 * wc[t].z; acc[1][3] += x1 * wc[t].w;
            }
        }
        #pragma unroll
        for (int r = 0; r < 2; r++) {
            int pos = pos0 + j0 + r;
            #pragma unroll
            for (int c = 0; c < 4; c++) {
                zs[j0 + r][i0 + c] = (pos < QLEN)
                    ? acc[r][c] + bproj[i0 + c] + skip[(size_t)(i0 + c) * QLEN + pos]
                    : 0.f;
            }
        }
    }
    __syncthreads();

    // ---- pre-LN (16 lanes/row) -> zs = zln ----
    {
        const int j = tid >> 4, ls = tid & 15;
        float mm = 0.f;
        #pragma unroll
        for (int d = ls; d < 128; d += 16) mm += zs[j][d];
        mm += __shfl_xor_sync(0xffffffffu, mm, 1);
        mm += __shfl_xor_sync(0xffffffffu, mm, 2);
        mm += __shfl_xor_sync(0xffffffffu, mm, 4);
        mm += __shfl_xor_sync(0xffffffffu, mm, 8);
        mm *= (1.f / 128.f);
        float vv = 0.f;
        #pragma unroll
        for (int d = ls; d < 128; d += 16) { float t = zs[j][d] - mm; vv += t * t; }
        vv += __shfl_xor_sync(0xffffffffu, vv, 1);
        vv += __shfl_xor_sync(0xffffffffu, vv, 2);
        vv += __shfl_xor_sync(0xffffffffu, vv, 4);
        vv += __shfl_xor_sync(0xffffffffu, vv, 8);
        vv *= (1.f / 128.f);
        if (ls == 0) { mu[j] = mm; rs[j] = rsqrtf(vv + 1e-5f); }
    }
    __syncthreads();

    #pragma unroll
    for (int it = 0; it < 8; it++) {
        int idx = tid + it * TTHREADS;
        int j = idx >> 7, d = idx & 127;
        zs[j][d] = (zs[j][d] - mu[j]) * rs[j] * pre_g[d] + pre_b[d];
    }
    __syncthreads();

    // ---- fc1 (128->256, split-col) + exact GELU -> h1; prefetch distance 4 ----
    {
        float acc[2][8];
        #pragma unroll
        for (int r = 0; r < 2; r++)
            #pragma unroll
            for (int c = 0; c < 8; c++) acc[r][c] = 0.f;

        const int j0 = (tid >> 5) * 2;
        const int la = (tid & 31) * 4;
        float4 wba[4], wbb[4];
        #pragma unroll
        for (int t = 0; t < 4; t++) {
            wba[t] = __ldg((const float4*)&g_w1T[t * 256 + la]);
            wbb[t] = __ldg((const float4*)&g_w1T[t * 256 + 128 + la]);
        }
        for (int d0 = 0; d0 < 128; d0 += 4) {
            float4 wca[4], wcb[4];
            #pragma unroll
            for (int t = 0; t < 4; t++) { wca[t] = wba[t]; wcb[t] = wbb[t]; }
            if (d0 + 4 < 128) {
                #pragma unroll
                for (int t = 0; t < 4; t++) {
                    wba[t] = __ldg((const float4*)&g_w1T[(d0 + 4 + t) * 256 + la]);
                    wbb[t] = __ldg((const float4*)&g_w1T[(d0 + 4 + t) * 256 + 128 + la]);
                }
            }
            #pragma unroll
            for (int t = 0; t < 4; t++) {
                float x0 = zs[j0][d0 + t];
                float x1 = zs[j0 + 1][d0 + t];
                acc[0][0] += x0 * wca[t].x; acc[0][1] += x0 * wca[t].y;
                acc[0][2] += x0 * wca[t].z; acc[0][3] += x0 * wca[t].w;
                acc[0][4] += x0 * wcb[t].x; acc[0][5] += x0 * wcb[t].y;
                acc[0][6] += x0 * wcb[t].z; acc[0][7] += x0 * wcb[t].w;
                acc[1][0] += x1 * wca[t].x; acc[1][1] += x1 * wca[t].y;
                acc[1][2] += x1 * wca[t].z; acc[1][3] += x1 * wca[t].w;
                acc[1][4] += x1 * wcb[t].x; acc[1][5] += x1 * wcb[t].y;
                acc[1][6] += x1 * wcb[t].z; acc[1][7] += x1 * wcb[t].w;
            }
        }
        #pragma unroll
        for (int r = 0; r < 2; r++) {
            #pragma unroll
            for (int c = 0; c < 4; c++) {
                float u = acc[r][c] + b1[la + c];
                h1[j0 + r][la + c] = 0.5f * u * (1.f + erff(u * 0.70710678118654752f));
                float u2 = acc[r][4 + c] + b1[128 + la + c];
                h1[j0 + r][128 + la + c] = 0.5f * u2 * (1.f + erff(u2 * 0.70710678118654752f));
            }
        }
    }
    __syncthreads();

    // ---- fc2 (256->128) + residual(zln) -> xs (reuse); prefetch distance 8 ----
    {
        float acc[2][4];
        #pragma unroll
        for (int r = 0; r < 2; r++)
            #pragma unroll
            for (int c = 0; c < 4; c++) acc[r][c] = 0.f;

        const int j0 = (tid >> 5) * 2;
        const int i0 = (tid & 31) * 4;
        float4 wb[8];
        #pragma unroll
        for (int t = 0; t < 8; t++)
            wb[t] = __ldg((const float4*)&g_w2T[t * 128 + i0]);

        for (int d0 = 0; d0 < 256; d0 += 8) {
            float4 wc[8];
            #pragma unroll
            for (int t = 0; t < 8; t++) wc[t] = wb[t];
            if (d0 + 8 < 256) {
                #pragma unroll
                for (int t = 0; t < 8; t++)
                    wb[t] = __ldg((const float4*)&g_w2T[(d0 + 8 + t) * 128 + i0]);
            }
            #pragma unroll
            for (int t = 0; t < 8; t++) {
                float x0 = h1[j0][d0 + t];
                float x1 = h1[j0 + 1][d0 + t];
                acc[0][0] += x0 * wc[t].x; acc[0][1] += x0 * wc[t].y;
                acc[0][2] += x0 * wc[t].z; acc[0][3] += x0 * wc[t].w;
                acc[1][0] += x1 * wc[t].x; acc[1][1] += x1 * wc[t].y;
                acc[1][2] += x1 * wc[t].z; acc[1][3] += x1 * wc[t].w;
            }
        }
        __syncthreads();   // before overwriting xs
        #pragma unroll
        for (int r = 0; r < 2; r++) {
            #pragma unroll
            for (int c = 0; c < 4; c++)
                xs[j0 + r][i0 + c] = acc[r][c] + b2[i0 + c] + zs[j0 + r][i0 + c];
        }
    }
    __syncthreads();

    // ---- post-LN (16 lanes/row) -> transposed store out[d*QLEN+pos] ----
    {
        const int j = tid >> 4, ls = tid & 15;
        float mm = 0.f;
        #pragma unroll
        for (int d = ls; d < 128; d += 16) mm += xs[j][d];
        mm += __shfl_xor_sync(0xffffffffu, mm, 1);
        mm += __shfl_xor_sync(0xffffffffu, mm, 2);
        mm += __shfl_xor_sync(0xffffffffu, mm, 4);
        mm += __shfl_xor_sync(0xffffffffu, mm, 8);
        mm *= (1.f / 128.f);
        float vv = 0.f;
        #pragma unroll
        for (int d = ls; d < 128; d += 16) { float t = xs[j][d] - mm; vv += t * t; }
        vv += __shfl_xor_sync(0xffffffffu, vv, 1);
        vv += __shfl_xor_sync(0xffffffffu, vv, 2);
        vv += __shfl_xor_sync(0xffffffffu, vv, 4);
        vv += __shfl_xor_sync(0xffffffffu, vv, 8);
        vv *= (1.f / 128.f);
        if (ls == 0) { mu[j] = mm; rs[j] = rsqrtf(vv + 1e-5f); }
    }
    __syncthreads();

    #pragma unroll
    for (int it = 0; it < 8; it++) {
        int idx = tid + it * TTHREADS;
        int d = idx >> 3, j = idx & 7;
        int pos = pos0 + j;
        if (pos < QLEN)
            out[(size_t)d * QLEN + pos] =
                (xs[j][d] - mu[j]) * rs[j] * post_g[d] + post_b[d];
    }
}

// ============================================================================
// launch
// ============================================================================
extern "C" void kernel_launch(void* const* d_in, const int* in_sizes, int n_in,
                              void* d_out, int out_size)
{
    const float* q      = (const float*)d_in[0];
    const float* k      = (const float*)d_in[1];
    const float* v      = (const float*)d_in[2];
    const float* Wl     = (const float*)d_in[3];
    const int*   vis    = (const int*)  d_in[4];
    const float* skip   = (const float*)d_in[5];
    const float* qn_g   = (const float*)d_in[6];
    const float* qn_b   = (const float*)d_in[7];
    const float* kn_g   = (const float*)d_in[8];
    const float* kn_b   = (const float*)d_in[9];
    const float* vn_g   = (const float*)d_in[10];
    const float* vn_b   = (const float*)d_in[11];
    const float* wq     = (const float*)d_in[12];
    const float* bq     = (const float*)d_in[13];
    const float* wk     = (const float*)d_in[14];
    const float* bk     = (const float*)d_in[15];
    const float* wv     = (const float*)d_in[16];
    const float* bv     = (const float*)d_in[17];
    const float* wproj  = (const float*)d_in[18];
    const float* bproj  = (const float*)d_in[19];
    const float* pre_g  = (const float*)d_in[20];
    const float* pre_b  = (const float*)d_in[21];
    const float* w1     = (const float*)d_in[22];
    const float* b1     = (const float*)d_in[23];
    const float* w2     = (const float*)d_in[24];
    const float* b2     = (const float*)d_in[25];
    const float* post_g = (const float*)d_in[26];
    const float* post_b = (const float*)d_in[27];
    float* out = (float*)d_out;

    const int ATTN_SMEM = NSTAGE * STAGEB;   // 89088
    cudaFuncSetAttribute(attn_kernel, cudaFuncAttributeMaxDynamicSharedMemorySize, ATTN_SMEM);

    const int QB = (QLEN + 31) / 32;            // 79
    const int TB = (QLEN + TROWS - 1) / TROWS;  // 313

    prep_weights<<<128, 256>>>(wq, wk, wv, wproj, w1, w2);

    qkv_fused<<<475, 256>>>(q, k, v, qn_g, qn_b, kn_g, kn_b, vn_g, vn_b,
                            bq, bk, bv);

    dim3 ag(QB, SPLITS);
    attn_kernel<<<ag, 256, ATTN_SMEM>>>(Wl, vis);

    tail_fused<<<TB, TTHREADS>>>(bproj, skip, pre_g, pre_b, b1, b2,
                                 post_g, post_b, out);
}

// round 13
// speedup vs baseline: 1.0373x; 1.0373x over previous
#include <cuda_runtime.h>
#include <cuda_bf16.h>
#include <cstdint>
#include <math.h>
#include <math_constants.h>

typedef unsigned int       u32;
typedef unsigned long long u64;

// ---------------- problem constants ----------------
#define QLEN   2500
#define NKLEN  6336
#define DMODEL 128
#define NHEADS 4
#define DHEAD  32
#define SPLITS 11
#define TPS    18           // 198 = 11 * 18 key tiles, exact
#define NKT    198
#define ATTN_SCALE 0.17677669529663688f
#define NEG_BIG (-3.402823466e38f)   // float32 finfo.min (reference semantics)

// attention pipeline smem layout (per stage)
#define KS_OFF   0
#define VS_OFF   10240
#define WS_OFF   20480
#define BV_OFF   25088
#define STAGEB   29696
#define NSTAGE   3

// ---------------- scratch ----------------
__device__ __nv_bfloat16 g_qbf[NHEADS * QLEN * DHEAD];
__device__ __nv_bfloat16 g_kbf[NHEADS * NKLEN * DHEAD];
__device__ __nv_bfloat16 g_vbf[NHEADS * NKLEN * DHEAD];
__device__ float g_pm[SPLITS * NHEADS * QLEN];
__device__ float g_ps[SPLITS * NHEADS * QLEN];
__device__ float g_pacc[SPLITS * NHEADS * QLEN * DHEAD];
// transposed weights: wT[d][col]
__device__ float g_wqT[128 * 128];
__device__ float g_wkT[128 * 128];
__device__ float g_wvT[128 * 128];
__device__ float g_wpT[128 * 128];
__device__ float g_w1T[128 * 256];
__device__ float g_w2T[256 * 128];

// ---------------- helpers ----------------
__device__ __forceinline__ u32 packbf(float lo, float hi) {
    u32 r;
    asm("cvt.rn.bf16x2.f32 %0, %1, %2;" : "=r"(r) : "f"(hi), "f"(lo));
    return r;
}

__device__ __forceinline__ void mma16816(float (&c)[4],
                                         u32 a0, u32 a1, u32 a2, u32 a3,
                                         u32 b0, u32 b1) {
    asm volatile(
        "mma.sync.aligned.m16n8k16.row.col.f32.bf16.bf16.f32 "
        "{%0,%1,%2,%3}, {%4,%5,%6,%7}, {%8,%9}, {%0,%1,%2,%3};"
        : "+f"(c[0]), "+f"(c[1]), "+f"(c[2]), "+f"(c[3])
        : "r"(a0), "r"(a1), "r"(a2), "r"(a3), "r"(b0), "r"(b1));
}

__device__ __forceinline__ void cpa16(void* dst, const void* src) {
    u32 d = (u32)__cvta_generic_to_shared(dst);
    asm volatile("cp.async.cg.shared.global [%0], [%1], 16;" :: "r"(d), "l"(src));
}
__device__ __forceinline__ void cp_commit() { asm volatile("cp.async.commit_group;"); }
__device__ __forceinline__ void cp_wait1()  { asm volatile("cp.async.wait_group 1;"); }

// ============================================================================
// Kernel 0: transpose weights into [d][col] layout (coalesced GEMM reads)
// ============================================================================
__global__ void __launch_bounds__(256)
prep_weights(const float* __restrict__ wq, const float* __restrict__ wk,
             const float* __restrict__ wv, const float* __restrict__ wp,
             const float* __restrict__ w1, const float* __restrict__ w2)
{
    int idx = blockIdx.x * 256 + threadIdx.x;    // 0..32767
    if (idx < 16384) {
        int r = idx >> 7, c = idx & 127;         // source [r][c] -> dst [c][r]
        g_wqT[c * 128 + r] = wq[idx];
        g_wkT[c * 128 + r] = wk[idx];
        g_wvT[c * 128 + r] = wv[idx];
        g_wpT[c * 128 + r] = wp[idx];
    }
    {   // w1: [256][128] -> [128][256]
        int r = idx >> 7, c = idx & 127;
        g_w1T[c * 256 + r] = w1[idx];
    }
    {   // w2: [128][256] -> [256][128]
        int r = idx >> 8, c = idx & 255;
        g_w2T[c * 128 + r] = w2[idx];
    }
}

// ============================================================================
// LN + 128x128 GEMM body (transposed weights) -> bf16 planar [h][pos][32]
// `scale` multiplies the final (GEMM+bias) result (used to pre-fold the
// attention 1/sqrt(dh) into Q; 1.0 for K/V).
// ============================================================================
__device__ __forceinline__ void ln_gemm_body(
    const float* __restrict__ x, int npos, int inner_pos,
    const float* __restrict__ gam, const float* __restrict__ bet,
    const float* __restrict__ wT, const float* __restrict__ bw,
    __nv_bfloat16* __restrict__ outb, int pos0, float scale,
    float (*xs)[132], float* mu, float* rs)
{
    const int tid = threadIdx.x;

    #pragma unroll
    for (int it = 0; it < 16; it++) {
        int idx = tid + it * 256;
        int d = idx >> 5, j = idx & 31;
        int pos = pos0 + j;
        float v = 0.f;
        if (pos < npos) {
            int n = pos / inner_pos;
            int p = pos - n * inner_pos;
            v = x[((size_t)n * DMODEL + d) * (size_t)inner_pos + p];
        }
        xs[j][d] = v;
    }
    __syncthreads();

    {
        const int j = tid >> 3, ls = tid & 7;
        float mm = 0.f;
        #pragma unroll
        for (int d = ls; d < 128; d += 8) mm += xs[j][d];
        mm += __shfl_xor_sync(0xffffffffu, mm, 1);
        mm += __shfl_xor_sync(0xffffffffu, mm, 2);
        mm += __shfl_xor_sync(0xffffffffu, mm, 4);
        mm *= (1.f / 128.f);
        float vv = 0.f;
        #pragma unroll
        for (int d = ls; d < 128; d += 8) { float t = xs[j][d] - mm; vv += t * t; }
        vv += __shfl_xor_sync(0xffffffffu, vv, 1);
        vv += __shfl_xor_sync(0xffffffffu, vv, 2);
        vv += __shfl_xor_sync(0xffffffffu, vv, 4);
        vv *= (1.f / 128.f);
        if (ls == 0) { mu[j] = mm; rs[j] = rsqrtf(vv + 1e-5f); }
    }
    __syncthreads();

    #pragma unroll
    for (int it = 0; it < 16; it++) {
        int idx = tid + it * 256;
        int j = idx >> 7, d = idx & 127;
        xs[j][d] = (xs[j][d] - mu[j]) * rs[j] * gam[d] + bet[d];
    }
    __syncthreads();

    float acc[4][4];
    #pragma unroll
    for (int r = 0; r < 4; r++)
        #pragma unroll
        for (int c = 0; c < 4; c++) acc[r][c] = 0.f;

    const int j0 = (tid >> 5) * 4;
    const int i0 = (tid & 31) * 4;
    for (int d0 = 0; d0 < 128; d0 += 4) {
        float4 xv[4];
        #pragma unroll
        for (int r = 0; r < 4; r++) xv[r] = *(const float4*)&xs[j0 + r][d0];
        #pragma unroll
        for (int dd = 0; dd < 4; dd++) {
            float4 wv = __ldg((const float4*)&wT[(d0 + dd) * 128 + i0]);
            #pragma unroll
            for (int r = 0; r < 4; r++) {
                float xr = (dd == 0) ? xv[r].x : (dd == 1) ? xv[r].y : (dd == 2) ? xv[r].z : xv[r].w;
                acc[r][0] += xr * wv.x;
                acc[r][1] += xr * wv.y;
                acc[r][2] += xr * wv.z;
                acc[r][3] += xr * wv.w;
            }
        }
    }
    const int h = i0 >> 5;
    const int dbase = i0 & 31;
    #pragma unroll
    for (int r = 0; r < 4; r++) {
        int pos = pos0 + j0 + r;
        if (pos < npos) {
            uint2 u;
            u.x = packbf((acc[r][0] + bw[i0 + 0]) * scale, (acc[r][1] + bw[i0 + 1]) * scale);
            u.y = packbf((acc[r][2] + bw[i0 + 2]) * scale, (acc[r][3] + bw[i0 + 3]) * scale);
            *(uint2*)&outb[((size_t)h * npos + pos) * DHEAD + dbase] = u;
        }
    }
}

// ============================================================================
// Kernel 1: fused QKV projections — one launch, 475 blocks
// Q pre-scaled by ATTN_SCALE so attn logits need no extra multiply.
// ============================================================================
__global__ void __launch_bounds__(256)
qkv_fused(const float* __restrict__ q, const float* __restrict__ k, const float* __restrict__ v,
          const float* __restrict__ qn_g, const float* __restrict__ qn_b,
          const float* __restrict__ kn_g, const float* __restrict__ kn_b,
          const float* __restrict__ vn_g, const float* __restrict__ vn_b,
          const float* __restrict__ bq, const float* __restrict__ bk,
          const float* __restrict__ bv)
{
    __shared__ float xs[32][132];
    __shared__ float mu[32], rs[32];
    int b = blockIdx.x;
    if (b < 79) {
        ln_gemm_body(q, QLEN, QLEN, qn_g, qn_b, g_wqT, bq, g_qbf, b * 32, ATTN_SCALE, xs, mu, rs);
    } else if (b < 277) {
        ln_gemm_body(k, NKLEN, 1056, kn_g, kn_b, g_wkT, bk, g_kbf, (b - 79) * 32, 1.f, xs, mu, rs);
    } else {
        ln_gemm_body(v, NKLEN, 1056, vn_g, vn_b, g_wvT, bv, g_vbf, (b - 277) * 32, 1.f, xs, mu, rs);
    }
}

// ============================================================================
// Kernel 2: HMMA bf16 flash attention, split-K, 3-stage cp.async pipeline.
// K fed via ldmatrix.x2 (kept from R12); softmax uses __expf (MUFU — reverted).
// ============================================================================
__device__ __forceinline__ void attn_issue_tile(char* stg, int qt, int k0,
                                                const float* __restrict__ Wl,
                                                const int* __restrict__ vis, int tid)
{
    #pragma unroll
    for (int c = tid; c < 512; c += 256) {
        int hh = c >> 7, key = (c >> 2) & 31, part = c & 3;
        size_t srcoff = ((size_t)(hh * NKLEN + k0 + key)) * DHEAD + part * 8;
        int doff = hh * 2560 + key * 80 + part * 16;
        cpa16(stg + KS_OFF + doff, g_kbf + srcoff);
        cpa16(stg + VS_OFF + doff, g_vbf + srcoff);
    }
    {
        int row = tid >> 3, part = tid & 7;
        int qq = qt * 32 + row; if (qq >= QLEN) qq = QLEN - 1;
        cpa16(stg + WS_OFF + row * 144 + part * 16, Wl  + (size_t)qq * NKLEN + k0 + part * 4);
        cpa16(stg + BV_OFF + row * 144 + part * 16, vis + (size_t)qq * NKLEN + k0 + part * 4);
    }
}

__global__ void __launch_bounds__(256, 2)
attn_kernel(const float* __restrict__ Wl, const int* __restrict__ vis)
{
    extern __shared__ char dsm[];

    const int tid = threadIdx.x;
    const int lane = tid & 31;
    const int wid = tid >> 5;
    const int h = wid & 3;
    const int rg = wid >> 2;
    const int g = lane >> 2;
    const int tx = lane & 3;
    const int qt = blockIdx.x;
    const int split = blockIdx.y;

    const int q0 = qt * 32 + rg * 16;
    const int r_lo = q0 + g;
    const int r_hi = q0 + g + 8;

    u32 aQ[2][4];
    #pragma unroll
    for (int kc = 0; kc < 2; kc++) {
        int c0 = kc * 16 + 2 * tx;
        aQ[kc][0] = (r_lo < QLEN) ? *(const u32*)&g_qbf[((size_t)h * QLEN + r_lo) * DHEAD + c0]     : 0u;
        aQ[kc][1] = (r_hi < QLEN) ? *(const u32*)&g_qbf[((size_t)h * QLEN + r_hi) * DHEAD + c0]     : 0u;
        aQ[kc][2] = (r_lo < QLEN) ? *(const u32*)&g_qbf[((size_t)h * QLEN + r_lo) * DHEAD + c0 + 8] : 0u;
        aQ[kc][3] = (r_hi < QLEN) ? *(const u32*)&g_qbf[((size_t)h * QLEN + r_hi) * DHEAD + c0 + 8] : 0u;
    }

    float acc[4][4];
    #pragma unroll
    for (int nc = 0; nc < 4; nc++)
        #pragma unroll
        for (int i = 0; i < 4; i++) acc[nc][i] = 0.f;
    float m0 = -CUDART_INF_F, m1 = -CUDART_INF_F, s0 = 0.f, s1 = 0.f;

    const int t0 = split * TPS;

    attn_issue_tile(dsm + 0 * STAGEB, qt, (t0 + 0) * 32, Wl, vis, tid);
    cp_commit();
    attn_issue_tile(dsm + 1 * STAGEB, qt, (t0 + 1) * 32, Wl, vis, tid);
    cp_commit();

    // ldmatrix row selector for K: lanes 0-7 -> matrix0 rows, 8-15 -> matrix1
    const int lm = lane & 15;
    const int lmrow = lm & 7;
    const int lmhalf = (lm >> 3) * 16;   // byte offset of second 8-col block

    for (int i = 0; i < TPS; i++) {
        cp_wait1();
        __syncthreads();
        char* stg = dsm + (i % NSTAGE) * STAGEB;

        float S[4][4];
        #pragma unroll
        for (int nc = 0; nc < 4; nc++) {
            S[nc][0] = 0.f; S[nc][1] = 0.f; S[nc][2] = 0.f; S[nc][3] = 0.f;
            #pragma unroll
            for (int kc = 0; kc < 2; kc++) {
                u32 kaddr = (u32)__cvta_generic_to_shared(
                    stg + KS_OFF + h * 2560 + (nc * 8 + lmrow) * 80 + kc * 32 + lmhalf);
                u32 b0, b1;
                asm volatile("ldmatrix.sync.aligned.m8n8.x2.shared.b16 {%0,%1}, [%2];"
                             : "=r"(b0), "=r"(b1) : "r"(kaddr));
                mma16816(S[nc], aQ[kc][0], aQ[kc][1], aQ[kc][2], aQ[kc][3], b0, b1);
            }
        }

        // logits: Q pre-scaled, so (vis==0 ? NEG_BIG : S) * W
        float l[4][4];
        const int wr_lo = rg * 16 + g;
        const int wr_hi = wr_lo + 8;
        #pragma unroll
        for (int nc = 0; nc < 4; nc++) {
            float2 wl = *(const float2*)(stg + WS_OFF + wr_lo * 144 + (nc * 8 + 2 * tx) * 4);
            float2 wh = *(const float2*)(stg + WS_OFF + wr_hi * 144 + (nc * 8 + 2 * tx) * 4);
            int2 bl = *(const int2*)(stg + BV_OFF + wr_lo * 144 + (nc * 8 + 2 * tx) * 4);
            int2 bh = *(const int2*)(stg + BV_OFF + wr_hi * 144 + (nc * 8 + 2 * tx) * 4);
            l[nc][0] = (bl.x == 0 ? NEG_BIG : S[nc][0]) * wl.x;
            l[nc][1] = (bl.y == 0 ? NEG_BIG : S[nc][1]) * wl.y;
            l[nc][2] = (bh.x == 0 ? NEG_BIG : S[nc][2]) * wh.x;
            l[nc][3] = (bh.y == 0 ? NEG_BIG : S[nc][3]) * wh.y;
        }

        float mx0 = fmaxf(fmaxf(l[0][0], l[0][1]), fmaxf(l[1][0], l[1][1]));
        mx0 = fmaxf(mx0, fmaxf(fmaxf(l[2][0], l[2][1]), fmaxf(l[3][0], l[3][1])));
        float mx1 = fmaxf(fmaxf(l[0][2], l[0][3]), fmaxf(l[1][2], l[1][3]));
        mx1 = fmaxf(mx1, fmaxf(fmaxf(l[2][2], l[2][3]), fmaxf(l[3][2], l[3][3])));
        mx0 = fmaxf(mx0, __shfl_xor_sync(0xffffffffu, mx0, 1));
        mx0 = fmaxf(mx0, __shfl_xor_sync(0xffffffffu, mx0, 2));
        mx1 = fmaxf(mx1, __shfl_xor_sync(0xffffffffu, mx1, 1));
        mx1 = fmaxf(mx1, __shfl_xor_sync(0xffffffffu, mx1, 2));
        float mn0 = fmaxf(m0, mx0);
        float mn1 = fmaxf(m1, mx1);
        float cr0 = __expf(m0 - mn0);
        float cr1 = __expf(m1 - mn1);
        m0 = mn0; m1 = mn1;
        s0 *= cr0; s1 *= cr1;
        #pragma unroll
        for (int nc = 0; nc < 4; nc++) {
            acc[nc][0] *= cr0; acc[nc][1] *= cr0;
            acc[nc][2] *= cr1; acc[nc][3] *= cr1;
        }
        float p[4][4];
        #pragma unroll
        for (int nc = 0; nc < 4; nc++) {
            p[nc][0] = __expf(l[nc][0] - m0);
            p[nc][1] = __expf(l[nc][1] - m0);
            p[nc][2] = __expf(l[nc][2] - m1);
            p[nc][3] = __expf(l[nc][3] - m1);
            s0 += p[nc][0] + p[nc][1];
            s1 += p[nc][2] + p[nc][3];
        }

        #pragma unroll
        for (int kc = 0; kc < 2; kc++) {
            u32 a0 = packbf(p[2 * kc][0],     p[2 * kc][1]);
            u32 a1 = packbf(p[2 * kc][2],     p[2 * kc][3]);
            u32 a2 = packbf(p[2 * kc + 1][0], p[2 * kc + 1][1]);
            u32 a3 = packbf(p[2 * kc + 1][2], p[2 * kc + 1][3]);
            int keyrow = kc * 16 + (lane & 15);
            #pragma unroll
            for (int nc = 0; nc < 4; nc++) {
                u32 addr = (u32)__cvta_generic_to_shared(
                    stg + VS_OFF + h * 2560 + keyrow * 80 + nc * 16);
                u32 b0, b1;
                asm volatile("ldmatrix.sync.aligned.m8n8.x2.trans.shared.b16 {%0,%1}, [%2];"
                             : "=r"(b0), "=r"(b1) : "r"(addr));
                mma16816(acc[nc], a0, a1, a2, a3, b0, b1);
            }
        }

        if (i + 2 < TPS)
            attn_issue_tile(dsm + ((i + 2) % NSTAGE) * STAGEB, qt, (t0 + i + 2) * 32, Wl, vis, tid);
        cp_commit();
    }

    s0 += __shfl_xor_sync(0xffffffffu, s0, 1);
    s0 += __shfl_xor_sync(0xffffffffu, s0, 2);
    s1 += __shfl_xor_sync(0xffffffffu, s1, 1);
    s1 += __shfl_xor_sync(0xffffffffu, s1, 2);

    const int base = (split * NHEADS + h) * QLEN;
    if (tx == 0) {
        if (r_lo < QLEN) { g_pm[base + r_lo] = m0; g_ps[base + r_lo] = s0; }
        if (r_hi < QLEN) { g_pm[base + r_hi] = m1; g_ps[base + r_hi] = s1; }
    }
    #pragma unroll
    for (int nc = 0; nc < 4; nc++) {
        if (r_lo < QLEN)
            *(float2*)&g_pacc[((size_t)(base + r_lo)) * DHEAD + nc * 8 + 2 * tx] =
                make_float2(acc[nc][0], acc[nc][1]);
        if (r_hi < QLEN)
            *(float2*)&g_pacc[((size_t)(base + r_hi)) * DHEAD + nc * 8 + 2 * tx] =
                make_float2(acc[nc][2], acc[nc][3]);
    }
}

// ============================================================================
// Kernel 3: fully fused tail — combine + proj + skip + pre-LN + fc1 + GELU
//           + fc2 + residual + post-LN + transposed store.
//           128 threads, 8 rows/block, 313 blocks.
// ============================================================================
#define TROWS 8
#define TTHREADS 128
__global__ void __launch_bounds__(TTHREADS)
tail_fused(const float* __restrict__ bproj, const float* __restrict__ skip,
           const float* __restrict__ pre_g, const float* __restrict__ pre_b,
           const float* __restrict__ b1, const float* __restrict__ b2,
           const float* __restrict__ post_g, const float* __restrict__ post_b,
           float* __restrict__ out)
{
    __shared__ float xs[TROWS][132];
    __shared__ float zs[TROWS][132];
    __shared__ float h1[TROWS][264];
    __shared__ float mu[TROWS], rs[TROWS];
    const int tid = threadIdx.x;
    const int pos0 = blockIdx.x * TROWS;

    // ---- combine split-K partials -> xs[row][h*32 + dh] (16 thr/row) ----
    {
        int row = tid >> 4;
        int h = (tid >> 2) & 3;
        int dh0 = (tid & 3) * 8;
        int qrow = pos0 + row;
        if (qrow < QLEN) {
            float M = -CUDART_INF_F;
            #pragma unroll
            for (int s = 0; s < SPLITS; s++)
                M = fmaxf(M, g_pm[(s * NHEADS + h) * QLEN + qrow]);
            float S = 0.f;
            float a[8];
            #pragma unroll
            for (int d = 0; d < 8; d++) a[d] = 0.f;
            #pragma unroll
            for (int s = 0; s < SPLITS; s++) {
                int p = (s * NHEADS + h) * QLEN + qrow;
                float e = __expf(g_pm[p] - M);
                S += g_ps[p] * e;
                const float* pa = &g_pacc[(size_t)p * DHEAD + dh0];
                #pragma unroll
                for (int d = 0; d < 8; d++) a[d] += pa[d] * e;
            }
            float inv = 1.f / S;
            #pragma unroll
            for (int d = 0; d < 8; d++) xs[row][h * 32 + dh0 + d] = a[d] * inv;
        } else {
            #pragma unroll
            for (int d = 0; d < 8; d++) xs[row][h * 32 + dh0 + d] = 0.f;
        }
    }
    __syncthreads();

    // ---- out-proj (128x128) + bias + skip -> zs; prefetch distance 8 ----
    {
        float acc[2][4];
        #pragma unroll
        for (int r = 0; r < 2; r++)
            #pragma unroll
            for (int c = 0; c < 4; c++) acc[r][c] = 0.f;

        const int j0 = (tid >> 5) * 2;
        const int i0 = (tid & 31) * 4;
        float4 wb[8];
        #pragma unroll
        for (int t = 0; t < 8; t++)
            wb[t] = __ldg((const float4*)&g_wpT[t * 128 + i0]);

        for (int d0 = 0; d0 < 128; d0 += 8) {
            float4 wc[8];
            #pragma unroll
            for (int t = 0; t < 8; t++) wc[t] = wb[t];
            if (d0 + 8 < 128) {
                #pragma unroll
                for (int t = 0; t < 8; t++)
                    wb[t] = __ldg((const float4*)&g_wpT[(d0 + 8 + t) * 128 + i0]);
            }
            #pragma unroll
            for (int t = 0; t < 8; t++) {
                float x0 = xs[j0][d0 + t];
                float x1 = xs[j0 + 1][d0 + t];
                acc[0][0] += x0 * wc[t].x; acc[0][1] += x0 * wc[t].y;
                acc[0][2] += x0 * wc[t].z; acc[0][3] += x0 * wc[t].w;
                acc[1][0] += x1 * wc[t].x; acc[1][1] += x1 * wc[t].y;
                acc[1][2] += x1 * wc[t].z; acc[1][3] += x1 * wc[t].w;
            }
        }
        #pragma unroll
        for (int r = 0; r < 2; r++) {
            int pos = pos0 + j0 + r;
            #pragma unroll
            for (int c = 0; c < 4; c++) {
                zs[j0 + r][i0 + c] = (pos < QLEN)
                    ? acc[r][c] + bproj[i0 + c] + skip[(size_t)(i0 + c) * QLEN + pos]
                    : 0.f;
            }
        }
    }
    __syncthreads();

    // ---- pre-LN (16 lanes/row) -> zs = zln ----
    {
        const int j = tid >> 4, ls = tid & 15;
        float mm = 0.f;
        #pragma unroll
        for (int d = ls; d < 128; d += 16) mm += zs[j][d];
        mm += __shfl_xor_sync(0xffffffffu, mm, 1);
        mm += __shfl_xor_sync(0xffffffffu, mm, 2);
        mm += __shfl_xor_sync(0xffffffffu, mm, 4);
        mm += __shfl_xor_sync(0xffffffffu, mm, 8);
        mm *= (1.f / 128.f);
        float vv = 0.f;
        #pragma unroll
        for (int d = ls; d < 128; d += 16) { float t = zs[j][d] - mm; vv += t * t; }
        vv += __shfl_xor_sync(0xffffffffu, vv, 1);
        vv += __shfl_xor_sync(0xffffffffu, vv, 2);
        vv += __shfl_xor_sync(0xffffffffu, vv, 4);
        vv += __shfl_xor_sync(0xffffffffu, vv, 8);
        vv *= (1.f / 128.f);
        if (ls == 0) { mu[j] = mm; rs[j] = rsqrtf(vv + 1e-5f); }
    }
    __syncthreads();

    #pragma unroll
    for (int it = 0; it < 8; it++) {
        int idx = tid + it * TTHREADS;
        int j = idx >> 7, d = idx & 127;
        zs[j][d] = (zs[j][d] - mu[j]) * rs[j] * pre_g[d] + pre_b[d];
    }
    __syncthreads();

    // ---- fc1 (128->256, split-col) + exact GELU -> h1; prefetch distance 4 ----
    {
        float acc[2][8];
        #pragma unroll
        for (int r = 0; r < 2; r++)
            #pragma unroll
            for (int c = 0; c < 8; c++) acc[r][c] = 0.f;

        const int j0 = (tid >> 5) * 2;
        const int la = (tid & 31) * 4;
        float4 wba[4], wbb[4];
        #pragma unroll
        for (int t = 0; t < 4; t++) {
            wba[t] = __ldg((const float4*)&g_w1T[t * 256 + la]);
            wbb[t] = __ldg((const float4*)&g_w1T[t * 256 + 128 + la]);
        }
        for (int d0 = 0; d0 < 128; d0 += 4) {
            float4 wca[4], wcb[4];
            #pragma unroll
            for (int t = 0; t < 4; t++) { wca[t] = wba[t]; wcb[t] = wbb[t]; }
            if (d0 + 4 < 128) {
                #pragma unroll
                for (int t = 0; t < 4; t++) {
                    wba[t] = __ldg((const float4*)&g_w1T[(d0 + 4 + t) * 256 + la]);
                    wbb[t] = __ldg((const float4*)&g_w1T[(d0 + 4 + t) * 256 + 128 + la]);
                }
            }
            #pragma unroll
            for (int t = 0; t < 4; t++) {
                float x0 = zs[j0][d0 + t];
                float x1 = zs[j0 + 1][d0 + t];
                acc[0][0] += x0 * wca[t].x; acc[0][1] += x0 * wca[t].y;
                acc[0][2] += x0 * wca[t].z; acc[0][3] += x0 * wca[t].w;
                acc[0][4] += x0 * wcb[t].x; acc[0][5] += x0 * wcb[t].y;
                acc[0][6] += x0 * wcb[t].z; acc[0][7] += x0 * wcb[t].w;
                acc[1][0] += x1 * wca[t].x; acc[1][1] += x1 * wca[t].y;
                acc[1][2] += x1 * wca[t].z; acc[1][3] += x1 * wca[t].w;
                acc[1][4] += x1 * wcb[t].x; acc[1][5] += x1 * wcb[t].y;
                acc[1][6] += x1 * wcb[t].z; acc[1][7] += x1 * wcb[t].w;
            }
        }
        #pragma unroll
        for (int r = 0; r < 2; r++) {
            #pragma unroll
            for (int c = 0; c < 4; c++) {
                float u = acc[r][c] + b1[la + c];
                h1[j0 + r][la + c] = 0.5f * u * (1.f + erff(u * 0.70710678118654752f));
                float u2 = acc[r][4 + c] + b1[128 + la + c];
                h1[j0 + r][128 + la + c] = 0.5f * u2 * (1.f + erff(u2 * 0.70710678118654752f));
            }
        }
    }
    __syncthreads();

    // ---- fc2 (256->128) + residual(zln) -> xs (reuse); prefetch distance 8 ----
    {
        float acc[2][4];
        #pragma unroll
        for (int r = 0; r < 2; r++)
            #pragma unroll
            for (int c = 0; c < 4; c++) acc[r][c] = 0.f;

        const int j0 = (tid >> 5) * 2;
        const int i0 = (tid & 31) * 4;
        float4 wb[8];
        #pragma unroll
        for (int t = 0; t < 8; t++)
            wb[t] = __ldg((const float4*)&g_w2T[t * 128 + i0]);

        for (int d0 = 0; d0 < 256; d0 += 8) {
            float4 wc[8];
            #pragma unroll
            for (int t = 0; t < 8; t++) wc[t] = wb[t];
            if (d0 + 8 < 256) {
                #pragma unroll
                for (int t = 0; t < 8; t++)
                    wb[t] = __ldg((const float4*)&g_w2T[(d0 + 8 + t) * 128 + i0]);
            }
            #pragma unroll
            for (int t = 0; t < 8; t++) {
                float x0 = h1[j0][d0 + t];
                float x1 = h1[j0 + 1][d0 + t];
                acc[0][0] += x0 * wc[t].x; acc[0][1] += x0 * wc[t].y;
                acc[0][2] += x0 * wc[t].z; acc[0][3] += x0 * wc[t].w;
                acc[1][0] += x1 * wc[t].x; acc[1][1] += x1 * wc[t].y;
                acc[1][2] += x1 * wc[t].z; acc[1][3] += x1 * wc[t].w;
            }
        }
        __syncthreads();   // before overwriting xs
        #pragma unroll
        for (int r = 0; r < 2; r++) {
            #pragma unroll
            for (int c = 0; c < 4; c++)
                xs[j0 + r][i0 + c] = acc[r][c] + b2[i0 + c] + zs[j0 + r][i0 + c];
        }
    }
    __syncthreads();

    // ---- post-LN (16 lanes/row) -> transposed store out[d*QLEN+pos] ----
    {
        const int j = tid >> 4, ls = tid & 15;
        float mm = 0.f;
        #pragma unroll
        for (int d = ls; d < 128; d += 16) mm += xs[j][d];
        mm += __shfl_xor_sync(0xffffffffu, mm, 1);
        mm += __shfl_xor_sync(0xffffffffu, mm, 2);
        mm += __shfl_xor_sync(0xffffffffu, mm, 4);
        mm += __shfl_xor_sync(0xffffffffu, mm, 8);
        mm *= (1.f / 128.f);
        float vv = 0.f;
        #pragma unroll
        for (int d = ls; d < 128; d += 16) { float t = xs[j][d] - mm; vv += t * t; }
        vv += __shfl_xor_sync(0xffffffffu, vv, 1);
        vv += __shfl_xor_sync(0xffffffffu, vv, 2);
        vv += __shfl_xor_sync(0xffffffffu, vv, 4);
        vv += __shfl_xor_sync(0xffffffffu, vv, 8);
        vv *= (1.f / 128.f);
        if (ls == 0) { mu[j] = mm; rs[j] = rsqrtf(vv + 1e-5f); }
    }
    __syncthreads();

    #pragma unroll
    for (int it = 0; it < 8; it++) {
        int idx = tid + it * TTHREADS;
        int d = idx >> 3, j = idx & 7;
        int pos = pos0 + j;
        if (pos < QLEN)
            out[(size_t)d * QLEN + pos] =
                (xs[j][d] - mu[j]) * rs[j] * post_g[d] + post_b[d];
    }
}

// ============================================================================
// launch
// ============================================================================
extern "C" void kernel_launch(void* const* d_in, const int* in_sizes, int n_in,
                              void* d_out, int out_size)
{
    const float* q      = (const float*)d_in[0];
    const float* k      = (const float*)d_in[1];
    const float* v      = (const float*)d_in[2];
    const float* Wl     = (const float*)d_in[3];
    const int*   vis    = (const int*)  d_in[4];
    const float* skip   = (const float*)d_in[5];
    const float* qn_g   = (const float*)d_in[6];
    const float* qn_b   = (const float*)d_in[7];
    const float* kn_g   = (const float*)d_in[8];
    const float* kn_b   = (const float*)d_in[9];
    const float* vn_g   = (const float*)d_in[10];
    const float* vn_b   = (const float*)d_in[11];
    const float* wq     = (const float*)d_in[12];
    const float* bq     = (const float*)d_in[13];
    const float* wk     = (const float*)d_in[14];
    const float* bk     = (const float*)d_in[15];
    const float* wv     = (const float*)d_in[16];
    const float* bv     = (const float*)d_in[17];
    const float* wproj  = (const float*)d_in[18];
    const float* bproj  = (const float*)d_in[19];
    const float* pre_g  = (const float*)d_in[20];
    const float* pre_b  = (const float*)d_in[21];
    const float* w1     = (const float*)d_in[22];
    const float* b1     = (const float*)d_in[23];
    const float* w2     = (const float*)d_in[24];
    const float* b2     = (const float*)d_in[25];
    const float* post_g = (const float*)d_in[26];
    const float* post_b = (const float*)d_in[27];
    float* out = (float*)d_out;

    const int ATTN_SMEM = NSTAGE * STAGEB;   // 89088
    cudaFuncSetAttribute(attn_kernel, cudaFuncAttributeMaxDynamicSharedMemorySize, ATTN_SMEM);

    const int QB = (QLEN + 31) / 32;            // 79
    const int TB = (QLEN + TROWS - 1) / TROWS;  // 313

    prep_weights<<<128, 256>>>(wq, wk, wv, wproj, w1, w2);

    qkv_fused<<<475, 256>>>(q, k, v, qn_g, qn_b, kn_g, kn_b, vn_g, vn_b,
                            bq, bk, bv);

    dim3 ag(QB, SPLITS);
    attn_kernel<<<ag, 256, ATTN_SMEM>>>(Wl, vis);

    tail_fused<<<TB, TTHREADS>>>(bproj, skip, pre_g, pre_b, b1, b2,
                                 post_g, post_b, out);
}

// round 14
// speedup vs baseline: 1.0642x; 1.0259x over previous
#include <cuda_runtime.h>
#include <cuda_bf16.h>
#include <cstdint>
#include <math.h>
#include <math_constants.h>

typedef unsigned int       u32;
typedef unsigned long long u64;

// ---------------- problem constants ----------------
#define QLEN   2500
#define NKLEN  6336
#define DMODEL 128
#define NHEADS 4
#define DHEAD  32
#define SPLITS 11
#define TPS    18           // 198 = 11 * 18 key tiles, exact
#define NKT    198
#define ATTN_SCALE 0.17677669529663688f
#define NEG_BIG (-3.402823466e38f)   // float32 finfo.min (reference semantics)

// attention pipeline smem layout (per stage)
#define KS_OFF   0
#define VS_OFF   10240
#define WS_OFF   20480
#define BV_OFF   25088
#define STAGEB   29696
#define NSTAGE   2

// ---------------- scratch ----------------
__device__ __nv_bfloat16 g_qbf[NHEADS * QLEN * DHEAD];
__device__ __nv_bfloat16 g_kbf[NHEADS * NKLEN * DHEAD];
__device__ __nv_bfloat16 g_vbf[NHEADS * NKLEN * DHEAD];
__device__ float g_pm[SPLITS * NHEADS * QLEN];
__device__ float g_ps[SPLITS * NHEADS * QLEN];
__device__ float g_pacc[SPLITS * NHEADS * QLEN * DHEAD];
// transposed weights: wT[d][col]
__device__ float g_wqT[128 * 128];
__device__ float g_wkT[128 * 128];
__device__ float g_wvT[128 * 128];
__device__ float g_wpT[128 * 128];
__device__ float g_w1T[128 * 256];
__device__ float g_w2T[256 * 128];

// ---------------- helpers ----------------
__device__ __forceinline__ u32 packbf(float lo, float hi) {
    u32 r;
    asm("cvt.rn.bf16x2.f32 %0, %1, %2;" : "=r"(r) : "f"(hi), "f"(lo));
    return r;
}

__device__ __forceinline__ void mma16816(float (&c)[4],
                                         u32 a0, u32 a1, u32 a2, u32 a3,
                                         u32 b0, u32 b1) {
    asm volatile(
        "mma.sync.aligned.m16n8k16.row.col.f32.bf16.bf16.f32 "
        "{%0,%1,%2,%3}, {%4,%5,%6,%7}, {%8,%9}, {%0,%1,%2,%3};"
        : "+f"(c[0]), "+f"(c[1]), "+f"(c[2]), "+f"(c[3])
        : "r"(a0), "r"(a1), "r"(a2), "r"(a3), "r"(b0), "r"(b1));
}

__device__ __forceinline__ void cpa16(void* dst, const void* src) {
    u32 d = (u32)__cvta_generic_to_shared(dst);
    asm volatile("cp.async.cg.shared.global [%0], [%1], 16;" :: "r"(d), "l"(src));
}
__device__ __forceinline__ void cp_commit() { asm volatile("cp.async.commit_group;"); }
__device__ __forceinline__ void cp_wait0()  { asm volatile("cp.async.wait_group 0;"); }

// ============================================================================
// Kernel 0: transpose weights into [d][col] layout (coalesced GEMM reads)
// ============================================================================
__global__ void __launch_bounds__(256)
prep_weights(const float* __restrict__ wq, const float* __restrict__ wk,
             const float* __restrict__ wv, const float* __restrict__ wp,
             const float* __restrict__ w1, const float* __restrict__ w2)
{
    int idx = blockIdx.x * 256 + threadIdx.x;    // 0..32767
    if (idx < 16384) {
        int r = idx >> 7, c = idx & 127;         // source [r][c] -> dst [c][r]
        g_wqT[c * 128 + r] = wq[idx];
        g_wkT[c * 128 + r] = wk[idx];
        g_wvT[c * 128 + r] = wv[idx];
        g_wpT[c * 128 + r] = wp[idx];
    }
    {   // w1: [256][128] -> [128][256]
        int r = idx >> 7, c = idx & 127;
        g_w1T[c * 256 + r] = w1[idx];
    }
    {   // w2: [128][256] -> [256][128]
        int r = idx >> 8, c = idx & 255;
        g_w2T[c * 128 + r] = w2[idx];
    }
}

// ============================================================================
// LN + 128x128 GEMM body (transposed weights) -> bf16 planar [h][pos][32]
// ============================================================================
__device__ __forceinline__ void ln_gemm_body(
    const float* __restrict__ x, int npos, int inner_pos,
    const float* __restrict__ gam, const float* __restrict__ bet,
    const float* __restrict__ wT, const float* __restrict__ bw,
    __nv_bfloat16* __restrict__ outb, int pos0, float scale,
    float (*xs)[132], float* mu, float* rs)
{
    const int tid = threadIdx.x;

    #pragma unroll
    for (int it = 0; it < 16; it++) {
        int idx = tid + it * 256;
        int d = idx >> 5, j = idx & 31;
        int pos = pos0 + j;
        float v = 0.f;
        if (pos < npos) {
            int n = pos / inner_pos;
            int p = pos - n * inner_pos;
            v = x[((size_t)n * DMODEL + d) * (size_t)inner_pos + p];
        }
        xs[j][d] = v;
    }
    __syncthreads();

    {
        const int j = tid >> 3, ls = tid & 7;
        float mm = 0.f;
        #pragma unroll
        for (int d = ls; d < 128; d += 8) mm += xs[j][d];
        mm += __shfl_xor_sync(0xffffffffu, mm, 1);
        mm += __shfl_xor_sync(0xffffffffu, mm, 2);
        mm += __shfl_xor_sync(0xffffffffu, mm, 4);
        mm *= (1.f / 128.f);
        float vv = 0.f;
        #pragma unroll
        for (int d = ls; d < 128; d += 8) { float t = xs[j][d] - mm; vv += t * t; }
        vv += __shfl_xor_sync(0xffffffffu, vv, 1);
        vv += __shfl_xor_sync(0xffffffffu, vv, 2);
        vv += __shfl_xor_sync(0xffffffffu, vv, 4);
        vv *= (1.f / 128.f);
        if (ls == 0) { mu[j] = mm; rs[j] = rsqrtf(vv + 1e-5f); }
    }
    __syncthreads();

    #pragma unroll
    for (int it = 0; it < 16; it++) {
        int idx = tid + it * 256;
        int j = idx >> 7, d = idx & 127;
        xs[j][d] = (xs[j][d] - mu[j]) * rs[j] * gam[d] + bet[d];
    }
    __syncthreads();

    float acc[4][4];
    #pragma unroll
    for (int r = 0; r < 4; r++)
        #pragma unroll
        for (int c = 0; c < 4; c++) acc[r][c] = 0.f;

    const int j0 = (tid >> 5) * 4;
    const int i0 = (tid & 31) * 4;
    for (int d0 = 0; d0 < 128; d0 += 4) {
        float4 xv[4];
        #pragma unroll
        for (int r = 0; r < 4; r++) xv[r] = *(const float4*)&xs[j0 + r][d0];
        #pragma unroll
        for (int dd = 0; dd < 4; dd++) {
            float4 wv = __ldg((const float4*)&wT[(d0 + dd) * 128 + i0]);
            #pragma unroll
            for (int r = 0; r < 4; r++) {
                float xr = (dd == 0) ? xv[r].x : (dd == 1) ? xv[r].y : (dd == 2) ? xv[r].z : xv[r].w;
                acc[r][0] += xr * wv.x;
                acc[r][1] += xr * wv.y;
                acc[r][2] += xr * wv.z;
                acc[r][3] += xr * wv.w;
            }
        }
    }
    const int h = i0 >> 5;
    const int dbase = i0 & 31;
    #pragma unroll
    for (int r = 0; r < 4; r++) {
        int pos = pos0 + j0 + r;
        if (pos < npos) {
            uint2 u;
            u.x = packbf((acc[r][0] + bw[i0 + 0]) * scale, (acc[r][1] + bw[i0 + 1]) * scale);
            u.y = packbf((acc[r][2] + bw[i0 + 2]) * scale, (acc[r][3] + bw[i0 + 3]) * scale);
            *(uint2*)&outb[((size_t)h * npos + pos) * DHEAD + dbase] = u;
        }
    }
}

// ============================================================================
// Kernel 1: fused QKV projections — one launch, 475 blocks
// Q pre-scaled by ATTN_SCALE so attn logits need no extra multiply.
// ============================================================================
__global__ void __launch_bounds__(256)
qkv_fused(const float* __restrict__ q, const float* __restrict__ k, const float* __restrict__ v,
          const float* __restrict__ qn_g, const float* __restrict__ qn_b,
          const float* __restrict__ kn_g, const float* __restrict__ kn_b,
          const float* __restrict__ vn_g, const float* __restrict__ vn_b,
          const float* __restrict__ bq, const float* __restrict__ bk,
          const float* __restrict__ bv)
{
    __shared__ float xs[32][132];
    __shared__ float mu[32], rs[32];
    int b = blockIdx.x;
    if (b < 79) {
        ln_gemm_body(q, QLEN, QLEN, qn_g, qn_b, g_wqT, bq, g_qbf, b * 32, ATTN_SCALE, xs, mu, rs);
    } else if (b < 277) {
        ln_gemm_body(k, NKLEN, 1056, kn_g, kn_b, g_wkT, bk, g_kbf, (b - 79) * 32, 1.f, xs, mu, rs);
    } else {
        ln_gemm_body(v, NKLEN, 1056, vn_g, vn_b, g_wvT, bv, g_vbf, (b - 277) * 32, 1.f, xs, mu, rs);
    }
}

// ============================================================================
// Kernel 2: HMMA bf16 flash attention, split-K.
// 2-stage double buffer (issue-before-compute), 3 blocks/SM (24 warps).
// ============================================================================
__device__ __forceinline__ void attn_issue_tile(char* stg, int qt, int k0,
                                                const float* __restrict__ Wl,
                                                const int* __restrict__ vis, int tid)
{
    #pragma unroll
    for (int c = tid; c < 512; c += 256) {
        int hh = c >> 7, key = (c >> 2) & 31, part = c & 3;
        size_t srcoff = ((size_t)(hh * NKLEN + k0 + key)) * DHEAD + part * 8;
        int doff = hh * 2560 + key * 80 + part * 16;
        cpa16(stg + KS_OFF + doff, g_kbf + srcoff);
        cpa16(stg + VS_OFF + doff, g_vbf + srcoff);
    }
    {
        int row = tid >> 3, part = tid & 7;
        int qq = qt * 32 + row; if (qq >= QLEN) qq = QLEN - 1;
        cpa16(stg + WS_OFF + row * 144 + part * 16, Wl  + (size_t)qq * NKLEN + k0 + part * 4);
        cpa16(stg + BV_OFF + row * 144 + part * 16, vis + (size_t)qq * NKLEN + k0 + part * 4);
    }
}

__global__ void __launch_bounds__(256, 3)
attn_kernel(const float* __restrict__ Wl, const int* __restrict__ vis)
{
    extern __shared__ char dsm[];

    const int tid = threadIdx.x;
    const int lane = tid & 31;
    const int wid = tid >> 5;
    const int h = wid & 3;
    const int rg = wid >> 2;
    const int g = lane >> 2;
    const int tx = lane & 3;
    const int qt = blockIdx.x;
    const int split = blockIdx.y;

    const int q0 = qt * 32 + rg * 16;
    const int r_lo = q0 + g;
    const int r_hi = q0 + g + 8;

    u32 aQ[2][4];
    #pragma unroll
    for (int kc = 0; kc < 2; kc++) {
        int c0 = kc * 16 + 2 * tx;
        aQ[kc][0] = (r_lo < QLEN) ? *(const u32*)&g_qbf[((size_t)h * QLEN + r_lo) * DHEAD + c0]     : 0u;
        aQ[kc][1] = (r_hi < QLEN) ? *(const u32*)&g_qbf[((size_t)h * QLEN + r_hi) * DHEAD + c0]     : 0u;
        aQ[kc][2] = (r_lo < QLEN) ? *(const u32*)&g_qbf[((size_t)h * QLEN + r_lo) * DHEAD + c0 + 8] : 0u;
        aQ[kc][3] = (r_hi < QLEN) ? *(const u32*)&g_qbf[((size_t)h * QLEN + r_hi) * DHEAD + c0 + 8] : 0u;
    }

    float acc[4][4];
    #pragma unroll
    for (int nc = 0; nc < 4; nc++)
        #pragma unroll
        for (int i = 0; i < 4; i++) acc[nc][i] = 0.f;
    float m0 = -CUDART_INF_F, m1 = -CUDART_INF_F, s0 = 0.f, s1 = 0.f;

    const int t0 = split * TPS;

    // prologue: prefetch tile 0
    attn_issue_tile(dsm, qt, t0 * 32, Wl, vis, tid);
    cp_commit();

    // ldmatrix row selector for K
    const int lm = lane & 15;
    const int lmrow = lm & 7;
    const int lmhalf = (lm >> 3) * 16;

    for (int i = 0; i < TPS; i++) {
        cp_wait0();          // tile i landed
        __syncthreads();     // all threads done with compute(i-1) & see tile i

        // issue tile i+1 into the other buffer — overlaps compute(i)
        if (i + 1 < TPS)
            attn_issue_tile(dsm + ((i + 1) & 1) * STAGEB, qt, (t0 + i + 1) * 32, Wl, vis, tid);
        cp_commit();

        char* stg = dsm + (i & 1) * STAGEB;

        float S[4][4];
        #pragma unroll
        for (int nc = 0; nc < 4; nc++) {
            S[nc][0] = 0.f; S[nc][1] = 0.f; S[nc][2] = 0.f; S[nc][3] = 0.f;
            #pragma unroll
            for (int kc = 0; kc < 2; kc++) {
                u32 kaddr = (u32)__cvta_generic_to_shared(
                    stg + KS_OFF + h * 2560 + (nc * 8 + lmrow) * 80 + kc * 32 + lmhalf);
                u32 b0, b1;
                asm volatile("ldmatrix.sync.aligned.m8n8.x2.shared.b16 {%0,%1}, [%2];"
                             : "=r"(b0), "=r"(b1) : "r"(kaddr));
                mma16816(S[nc], aQ[kc][0], aQ[kc][1], aQ[kc][2], aQ[kc][3], b0, b1);
            }
        }

        float l[4][4];
        const int wr_lo = rg * 16 + g;
        const int wr_hi = wr_lo + 8;
        #pragma unroll
        for (int nc = 0; nc < 4; nc++) {
            float2 wl = *(const float2*)(stg + WS_OFF + wr_lo * 144 + (nc * 8 + 2 * tx) * 4);
            float2 wh = *(const float2*)(stg + WS_OFF + wr_hi * 144 + (nc * 8 + 2 * tx) * 4);
            int2 bl = *(const int2*)(stg + BV_OFF + wr_lo * 144 + (nc * 8 + 2 * tx) * 4);
            int2 bh = *(const int2*)(stg + BV_OFF + wr_hi * 144 + (nc * 8 + 2 * tx) * 4);
            l[nc][0] = (bl.x == 0 ? NEG_BIG : S[nc][0]) * wl.x;
            l[nc][1] = (bl.y == 0 ? NEG_BIG : S[nc][1]) * wl.y;
            l[nc][2] = (bh.x == 0 ? NEG_BIG : S[nc][2]) * wh.x;
            l[nc][3] = (bh.y == 0 ? NEG_BIG : S[nc][3]) * wh.y;
        }

        float mx0 = fmaxf(fmaxf(l[0][0], l[0][1]), fmaxf(l[1][0], l[1][1]));
        mx0 = fmaxf(mx0, fmaxf(fmaxf(l[2][0], l[2][1]), fmaxf(l[3][0], l[3][1])));
        float mx1 = fmaxf(fmaxf(l[0][2], l[0][3]), fmaxf(l[1][2], l[1][3]));
        mx1 = fmaxf(mx1, fmaxf(fmaxf(l[2][2], l[2][3]), fmaxf(l[3][2], l[3][3])));
        mx0 = fmaxf(mx0, __shfl_xor_sync(0xffffffffu, mx0, 1));
        mx0 = fmaxf(mx0, __shfl_xor_sync(0xffffffffu, mx0, 2));
        mx1 = fmaxf(mx1, __shfl_xor_sync(0xffffffffu, mx1, 1));
        mx1 = fmaxf(mx1, __shfl_xor_sync(0xffffffffu, mx1, 2));
        float mn0 = fmaxf(m0, mx0);
        float mn1 = fmaxf(m1, mx1);
        float cr0 = __expf(m0 - mn0);
        float cr1 = __expf(m1 - mn1);
        m0 = mn0; m1 = mn1;
        s0 *= cr0; s1 *= cr1;
        #pragma unroll
        for (int nc = 0; nc < 4; nc++) {
            acc[nc][0] *= cr0; acc[nc][1] *= cr0;
            acc[nc][2] *= cr1; acc[nc][3] *= cr1;
        }
        float p[4][4];
        #pragma unroll
        for (int nc = 0; nc < 4; nc++) {
            p[nc][0] = __expf(l[nc][0] - m0);
            p[nc][1] = __expf(l[nc][1] - m0);
            p[nc][2] = __expf(l[nc][2] - m1);
            p[nc][3] = __expf(l[nc][3] - m1);
            s0 += p[nc][0] + p[nc][1];
            s1 += p[nc][2] + p[nc][3];
        }

        #pragma unroll
        for (int kc = 0; kc < 2; kc++) {
            u32 a0 = packbf(p[2 * kc][0],     p[2 * kc][1]);
            u32 a1 = packbf(p[2 * kc][2],     p[2 * kc][3]);
            u32 a2 = packbf(p[2 * kc + 1][0], p[2 * kc + 1][1]);
            u32 a3 = packbf(p[2 * kc + 1][2], p[2 * kc + 1][3]);
            int keyrow = kc * 16 + (lane & 15);
            #pragma unroll
            for (int nc = 0; nc < 4; nc++) {
                u32 addr = (u32)__cvta_generic_to_shared(
                    stg + VS_OFF + h * 2560 + keyrow * 80 + nc * 16);
                u32 b0, b1;
                asm volatile("ldmatrix.sync.aligned.m8n8.x2.trans.shared.b16 {%0,%1}, [%2];"
                             : "=r"(b0), "=r"(b1) : "r"(addr));
                mma16816(acc[nc], a0, a1, a2, a3, b0, b1);
            }
        }
    }

    s0 += __shfl_xor_sync(0xffffffffu, s0, 1);
    s0 += __shfl_xor_sync(0xffffffffu, s0, 2);
    s1 += __shfl_xor_sync(0xffffffffu, s1, 1);
    s1 += __shfl_xor_sync(0xffffffffu, s1, 2);

    const int base = (split * NHEADS + h) * QLEN;
    if (tx == 0) {
        if (r_lo < QLEN) { g_pm[base + r_lo] = m0; g_ps[base + r_lo] = s0; }
        if (r_hi < QLEN) { g_pm[base + r_hi] = m1; g_ps[base + r_hi] = s1; }
    }
    #pragma unroll
    for (int nc = 0; nc < 4; nc++) {
        if (r_lo < QLEN)
            *(float2*)&g_pacc[((size_t)(base + r_lo)) * DHEAD + nc * 8 + 2 * tx] =
                make_float2(acc[nc][0], acc[nc][1]);
        if (r_hi < QLEN)
            *(float2*)&g_pacc[((size_t)(base + r_hi)) * DHEAD + nc * 8 + 2 * tx] =
                make_float2(acc[nc][2], acc[nc][3]);
    }
}

// ============================================================================
// Kernel 3: fully fused tail — combine + proj + skip + pre-LN + fc1 + GELU
//           + fc2 + residual + post-LN + transposed store.
//           128 threads, 8 rows/block, 313 blocks.
// ============================================================================
#define TROWS 8
#define TTHREADS 128
__global__ void __launch_bounds__(TTHREADS)
tail_fused(const float* __restrict__ bproj, const float* __restrict__ skip,
           const float* __restrict__ pre_g, const float* __restrict__ pre_b,
           const float* __restrict__ b1, const float* __restrict__ b2,
           const float* __restrict__ post_g, const float* __restrict__ post_b,
           float* __restrict__ out)
{
    __shared__ float xs[TROWS][132];
    __shared__ float zs[TROWS][132];
    __shared__ float h1[TROWS][264];
    __shared__ float mu[TROWS], rs[TROWS];
    const int tid = threadIdx.x;
    const int pos0 = blockIdx.x * TROWS;

    // ---- combine split-K partials -> xs[row][h*32 + dh] (16 thr/row) ----
    {
        int row = tid >> 4;
        int h = (tid >> 2) & 3;
        int dh0 = (tid & 3) * 8;
        int qrow = pos0 + row;
        if (qrow < QLEN) {
            float M = -CUDART_INF_F;
            #pragma unroll
            for (int s = 0; s < SPLITS; s++)
                M = fmaxf(M, g_pm[(s * NHEADS + h) * QLEN + qrow]);
            float S = 0.f;
            float a[8];
            #pragma unroll
            for (int d = 0; d < 8; d++) a[d] = 0.f;
            #pragma unroll
            for (int s = 0; s < SPLITS; s++) {
                int p = (s * NHEADS + h) * QLEN + qrow;
                float e = __expf(g_pm[p] - M);
                S += g_ps[p] * e;
                const float* pa = &g_pacc[(size_t)p * DHEAD + dh0];
                #pragma unroll
                for (int d = 0; d < 8; d++) a[d] += pa[d] * e;
            }
            float inv = 1.f / S;
            #pragma unroll
            for (int d = 0; d < 8; d++) xs[row][h * 32 + dh0 + d] = a[d] * inv;
        } else {
            #pragma unroll
            for (int d = 0; d < 8; d++) xs[row][h * 32 + dh0 + d] = 0.f;
        }
    }
    __syncthreads();

    // ---- out-proj (128x128) + bias + skip -> zs; prefetch distance 8 ----
    {
        float acc[2][4];
        #pragma unroll
        for (int r = 0; r < 2; r++)
            #pragma unroll
            for (int c = 0; c < 4; c++) acc[r][c] = 0.f;

        const int j0 = (tid >> 5) * 2;
        const int i0 = (tid & 31) * 4;
        float4 wb[8];
        #pragma unroll
        for (int t = 0; t < 8; t++)
            wb[t] = __ldg((const float4*)&g_wpT[t * 128 + i0]);

        for (int d0 = 0; d0 < 128; d0 += 8) {
            float4 wc[8];
            #pragma unroll
            for (int t = 0; t < 8; t++) wc[t] = wb[t];
            if (d0 + 8 < 128) {
                #pragma unroll
                for (int t = 0; t < 8; t++)
                    wb[t] = __ldg((const float4*)&g_wpT[(d0 + 8 + t) * 128 + i0]);
            }
            #pragma unroll
            for (int t = 0; t < 8; t++) {
                float x0 = xs[j0][d0 + t];
                float x1 = xs[j0 + 1][d0 + t];
                acc[0][0] += x0 * wc[t].x; acc[0][1] += x0 * wc[t].y;
                acc[0][2] += x0 * wc[t].z; acc[0][3] += x0 * wc[t].w;
                acc[1][0] += x1 * wc[t].x; acc[1][1] += x1 * wc[t].y;
                acc[1][2] += x1 * wc[t].z; acc[1][3] += x1 * wc[t].w;
            }
        }
        #pragma unroll
        for (int r = 0; r < 2; r++) {
            int pos = pos0 + j0 + r;
            #pragma unroll
            for (int c = 0; c < 4; c++) {
                zs[j0 + r][i0 + c] = (pos < QLEN)
                    ? acc[r][c] + bproj[i0 + c] + skip[(size_t)(i0 + c) * QLEN + pos]
                    : 0.f;
            }
        }
    }
    __syncthreads();

    // ---- pre-LN (16 lanes/row) -> zs = zln ----
    {
        const int j = tid >> 4, ls = tid & 15;
        float mm = 0.f;
        #pragma unroll
        for (int d = ls; d < 128; d += 16) mm += zs[j][d];
        mm += __shfl_xor_sync(0xffffffffu, mm, 1);
        mm += __shfl_xor_sync(0xffffffffu, mm, 2);
        mm += __shfl_xor_sync(0xffffffffu, mm, 4);
        mm += __shfl_xor_sync(0xffffffffu, mm, 8);
        mm *= (1.f / 128.f);
        float vv = 0.f;
        #pragma unroll
        for (int d = ls; d < 128; d += 16) { float t = zs[j][d] - mm; vv += t * t; }
        vv += __shfl_xor_sync(0xffffffffu, vv, 1);
        vv += __shfl_xor_sync(0xffffffffu, vv, 2);
        vv += __shfl_xor_sync(0xffffffffu, vv, 4);
        vv += __shfl_xor_sync(0xffffffffu, vv, 8);
        vv *= (1.f / 128.f);
        if (ls == 0) { mu[j] = mm; rs[j] = rsqrtf(vv + 1e-5f); }
    }
    __syncthreads();

    #pragma unroll
    for (int it = 0; it < 8; it++) {
        int idx = tid + it * TTHREADS;
        int j = idx >> 7, d = idx & 127;
        zs[j][d] = (zs[j][d] - mu[j]) * rs[j] * pre_g[d] + pre_b[d];
    }
    __syncthreads();

    // ---- fc1 (128->256, split-col) + exact GELU -> h1; prefetch distance 4 ----
    {
        float acc[2][8];
        #pragma unroll
        for (int r = 0; r < 2; r++)
            #pragma unroll
            for (int c = 0; c < 8; c++) acc[r][c] = 0.f;

        const int j0 = (tid >> 5) * 2;
        const int la = (tid & 31) * 4;
        float4 wba[4], wbb[4];
        #pragma unroll
        for (int t = 0; t < 4; t++) {
            wba[t] = __ldg((const float4*)&g_w1T[t * 256 + la]);
            wbb[t] = __ldg((const float4*)&g_w1T[t * 256 + 128 + la]);
        }
        for (int d0 = 0; d0 < 128; d0 += 4) {
            float4 wca[4], wcb[4];
            #pragma unroll
            for (int t = 0; t < 4; t++) { wca[t] = wba[t]; wcb[t] = wbb[t]; }
            if (d0 + 4 < 128) {
                #pragma unroll
                for (int t = 0; t < 4; t++) {
                    wba[t] = __ldg((const float4*)&g_w1T[(d0 + 4 + t) * 256 + la]);
                    wbb[t] = __ldg((const float4*)&g_w1T[(d0 + 4 + t) * 256 + 128 + la]);
                }
            }
            #pragma unroll
            for (int t = 0; t < 4; t++) {
                float x0 = zs[j0][d0 + t];
                float x1 = zs[j0 + 1][d0 + t];
                acc[0][0] += x0 * wca[t].x; acc[0][1] += x0 * wca[t].y;
                acc[0][2] += x0 * wca[t].z; acc[0][3] += x0 * wca[t].w;
                acc[0][4] += x0 * wcb[t].x; acc[0][5] += x0 * wcb[t].y;
                acc[0][6] += x0 * wcb[t].z; acc[0][7] += x0 * wcb[t].w;
                acc[1][0] += x1 * wca[t].x; acc[1][1] += x1 * wca[t].y;
                acc[1][2] += x1 * wca[t].z; acc[1][3] += x1 * wca[t].w;
                acc[1][4] += x1 * wcb[t].x; acc[1][5] += x1 * wcb[t].y;
                acc[1][6] += x1 * wcb[t].z; acc[1][7] += x1 * wcb[t].w;
            }
        }
        #pragma unroll
        for (int r = 0; r < 2; r++) {
            #pragma unroll
            for (int c = 0; c < 4; c++) {
                float u = acc[r][c] + b1[la + c];
                h1[j0 + r][la + c] = 0.5f * u * (1.f + erff(u * 0.70710678118654752f));
                float u2 = acc[r][4 + c] + b1[128 + la + c];
                h1[j0 + r][128 + la + c] = 0.5f * u2 * (1.f + erff(u2 * 0.70710678118654752f));
            }
        }
    }
    __syncthreads();

    // ---- fc2 (256->128) + residual(zln) -> xs (reuse); prefetch distance 8 ----
    {
        float acc[2][4];
        #pragma unroll
        for (int r = 0; r < 2; r++)
            #pragma unroll
            for (int c = 0; c < 4; c++) acc[r][c] = 0.f;

        const int j0 = (tid >> 5) * 2;
        const int i0 = (tid & 31) * 4;
        float4 wb[8];
        #pragma unroll
        for (int t = 0; t < 8; t++)
            wb[t] = __ldg((const float4*)&g_w2T[t * 128 + i0]);

        for (int d0 = 0; d0 < 256; d0 += 8) {
            float4 wc[8];
            #pragma unroll
            for (int t = 0; t < 8; t++) wc[t] = wb[t];
            if (d0 + 8 < 256) {
                #pragma unroll
                for (int t = 0; t < 8; t++)
                    wb[t] = __ldg((const float4*)&g_w2T[(d0 + 8 + t) * 128 + i0]);
            }
            #pragma unroll
            for (int t = 0; t < 8; t++) {
                float x0 = h1[j0][d0 + t];
                float x1 = h1[j0 + 1][d0 + t];
                acc[0][0] += x0 * wc[t].x; acc[0][1] += x0 * wc[t].y;
                acc[0][2] += x0 * wc[t].z; acc[0][3] += x0 * wc[t].w;
                acc[1][0] += x1 * wc[t].x; acc[1][1] += x1 * wc[t].y;
                acc[1][2] += x1 * wc[t].z; acc[1][3] += x1 * wc[t].w;
            }
        }
        __syncthreads();   // before overwriting xs
        #pragma unroll
        for (int r = 0; r < 2; r++) {
            #pragma unroll
            for (int c = 0; c < 4; c++)
                xs[j0 + r][i0 + c] = acc[r][c] + b2[i0 + c] + zs[j0 + r][i0 + c];
        }
    }
    __syncthreads();

    // ---- post-LN (16 lanes/row) -> transposed store out[d*QLEN+pos] ----
    {
        const int j = tid >> 4, ls = tid & 15;
        float mm = 0.f;
        #pragma unroll
        for (int d = ls; d < 128; d += 16) mm += xs[j][d];
        mm += __shfl_xor_sync(0xffffffffu, mm, 1);
        mm += __shfl_xor_sync(0xffffffffu, mm, 2);
        mm += __shfl_xor_sync(0xffffffffu, mm, 4);
        mm += __shfl_xor_sync(0xffffffffu, mm, 8);
        mm *= (1.f / 128.f);
        float vv = 0.f;
        #pragma unroll
        for (int d = ls; d < 128; d += 16) { float t = xs[j][d] - mm; vv += t * t; }
        vv += __shfl_xor_sync(0xffffffffu, vv, 1);
        vv += __shfl_xor_sync(0xffffffffu, vv, 2);
        vv += __shfl_xor_sync(0xffffffffu, vv, 4);
        vv += __shfl_xor_sync(0xffffffffu, vv, 8);
        vv *= (1.f / 128.f);
        if (ls == 0) { mu[j] = mm; rs[j] = rsqrtf(vv + 1e-5f); }
    }
    __syncthreads();

    #pragma unroll
    for (int it = 0; it < 8; it++) {
        int idx = tid + it * TTHREADS;
        int d = idx >> 3, j = idx & 7;
        int pos = pos0 + j;
        if (pos < QLEN)
            out[(size_t)d * QLEN + pos] =
                (xs[j][d] - mu[j]) * rs[j] * post_g[d] + post_b[d];
    }
}

// ============================================================================
// launch
// ============================================================================
extern "C" void kernel_launch(void* const* d_in, const int* in_sizes, int n_in,
                              void* d_out, int out_size)
{
    const float* q      = (const float*)d_in[0];
    const float* k      = (const float*)d_in[1];
    const float* v      = (const float*)d_in[2];
    const float* Wl     = (const float*)d_in[3];
    const int*   vis    = (const int*)  d_in[4];
    const float* skip   = (const float*)d_in[5];
    const float* qn_g   = (const float*)d_in[6];
    const float* qn_b   = (const float*)d_in[7];
    const float* kn_g   = (const float*)d_in[8];
    const float* kn_b   = (const float*)d_in[9];
    const float* vn_g   = (const float*)d_in[10];
    const float* vn_b   = (const float*)d_in[11];
    const float* wq     = (const float*)d_in[12];
    const float* bq     = (const float*)d_in[13];
    const float* wk     = (const float*)d_in[14];
    const float* bk     = (const float*)d_in[15];
    const float* wv     = (const float*)d_in[16];
    const float* bv     = (const float*)d_in[17];
    const float* wproj  = (const float*)d_in[18];
    const float* bproj  = (const float*)d_in[19];
    const float* pre_g  = (const float*)d_in[20];
    const float* pre_b  = (const float*)d_in[21];
    const float* w1     = (const float*)d_in[22];
    const float* b1     = (const float*)d_in[23];
    const float* w2     = (const float*)d_in[24];
    const float* b2     = (const float*)d_in[25];
    const float* post_g = (const float*)d_in[26];
    const float* post_b = (const float*)d_in[27];
    float* out = (float*)d_out;

    const int ATTN_SMEM = NSTAGE * STAGEB;   // 59392
    cudaFuncSetAttribute(attn_kernel, cudaFuncAttributeMaxDynamicSharedMemorySize, ATTN_SMEM);

    const int QB = (QLEN + 31) / 32;            // 79
    const int TB = (QLEN + TROWS - 1) / TROWS;  // 313

    prep_weights<<<128, 256>>>(wq, wk, wv, wproj, w1, w2);

    qkv_fused<<<475, 256>>>(q, k, v, qn_g, qn_b, kn_g, kn_b, vn_g, vn_b,
                            bq, bk, bv);

    dim3 ag(QB, SPLITS);
    attn_kernel<<<ag, 256, ATTN_SMEM>>>(Wl, vis);

    tail_fused<<<TB, TTHREADS>>>(bproj, skip, pre_g, pre_b, b1, b2,
                                 post_g, post_b, out);
}